// round 13
// baseline (speedup 1.0000x reference)
#include <cuda_runtime.h>
#include <math.h>
#include <stdint.h>

// ---------------------------------------------------------------------------
// ExpressionBert forward. tf32 mma.sync + cp.async pipelines.
// Round 13: base = round 11 (best, scalar-LDS fragments). Single change:
// fused_attn rewritten for 512 threads / 16 warps (warp tile 16x128 phase 1,
// 16x64 phase 2) to double resident warps under its 169KB smem (1 CTA/SM).
// ---------------------------------------------------------------------------

#define LNUM   4
#define DIM    512
#define NHEAD  4
#define DHD    128
#define FFI    128
#define SEQ    256
#define BATCH  128
#define NFEAT  6
#define TOK    (BATCH*SEQ)          // 32768
#define ROWSBH (BATCH*NHEAD*SEQ)    // 131072
#define QCOLS  384
#define DPAD   608

#define SM_SCALE 0.08838834764831845f  // 1/sqrt(128)

// ------------------------- static device scratch ---------------------------
__device__ float g_X  [TOK*DIM];
__device__ float g_Q  [TOK*DIM];
__device__ float g_K  [TOK*DIM];
__device__ float g_V  [TOK*DIM];
__device__ float g_CTX[TOK*DIM];
__device__ float g_TMP[TOK*DIM];
__device__ float g_Hb [TOK*FFI];
__device__ float g_QD [(size_t)ROWSBH*QCOLS];
__device__ float g_KD [(size_t)ROWSBH*QCOLS];
__device__ float g_dP [DPAD*DHD];

__device__ float g_WqT [LNUM*DIM*DIM];
__device__ float g_WkT [LNUM*DIM*DIM];
__device__ float g_WvT [LNUM*DIM*DIM];
__device__ float g_WoT [LNUM*DIM*DIM];
__device__ float g_WiT [LNUM*FFI*DIM];
__device__ float g_Wo2T[LNUM*DIM*FFI];

// ------------------------------ helpers -------------------------------------
__device__ __forceinline__ uint32_t smem_u32(const void* p) {
    uint32_t a;
    asm("{ .reg .u64 t; cvta.to.shared.u64 t, %1; cvt.u32.u64 %0, t; }"
        : "=r"(a) : "l"(p));
    return a;
}

__device__ __forceinline__ float gelu_exact(float x) {
    return 0.5f * x * (1.0f + erff(x * 0.70710678118654752440f));
}

__device__ __forceinline__ float tf32_rna(float f) {
    uint32_t u;
    asm("cvt.rna.tf32.f32 %0, %1;" : "=r"(u) : "f"(f));
    return __uint_as_float(u);
}

__device__ __forceinline__ void mma_tf32(float* d, const uint32_t* a,
                                         const uint32_t* b) {
    asm volatile(
        "mma.sync.aligned.m16n8k8.row.col.f32.tf32.tf32.f32 "
        "{%0,%1,%2,%3}, {%4,%5,%6,%7}, {%8,%9}, {%0,%1,%2,%3};"
        : "+f"(d[0]), "+f"(d[1]), "+f"(d[2]), "+f"(d[3])
        : "r"(a[0]), "r"(a[1]), "r"(a[2]), "r"(a[3]), "r"(b[0]), "r"(b[1]));
}

__device__ __forceinline__ void cp16(uint32_t saddr, const void* gptr) {
    asm volatile("cp.async.cg.shared.global [%0], [%1], 16;"
                 :: "r"(saddr), "l"(gptr) : "memory");
}
#define CP_COMMIT() asm volatile("cp.async.commit_group;" ::: "memory")
#define CP_WAIT1()  asm volatile("cp.async.wait_group 1;" ::: "memory")

#define SST 36
#define STAGEF 9216
#define NSTAGE 3

#define FRAG_COMPUTE(sA, sB)                                                   \
    _Pragma("unroll")                                                          \
    for (int kk = 0; kk < 32; kk += 8) {                                       \
        uint32_t af[2][4];                                                     \
        _Pragma("unroll")                                                      \
        for (int mt = 0; mt < 2; mt++) {                                       \
            int r = mbase + mt * 16 + g;                                       \
            af[mt][0] = (sA)[r * SST + kk + t];                                \
            af[mt][1] = (sA)[(r + 8) * SST + kk + t];                          \
            af[mt][2] = (sA)[r * SST + kk + t + 4];                            \
            af[mt][3] = (sA)[(r + 8) * SST + kk + t + 4];                      \
        }                                                                      \
        uint32_t bf[8][2];                                                     \
        _Pragma("unroll")                                                      \
        for (int nt = 0; nt < 8; nt++) {                                       \
            int r = nbase + nt * 8 + g;                                        \
            bf[nt][0] = (sB)[r * SST + kk + t];                                \
            bf[nt][1] = (sB)[r * SST + kk + t + 4];                            \
        }                                                                      \
        _Pragma("unroll")                                                      \
        for (int mt = 0; mt < 2; mt++)                                         \
            _Pragma("unroll")                                                  \
            for (int nt = 0; nt < 8; nt++)                                     \
                mma_tf32(acc[mt][nt], af[mt], bf[nt]);                         \
    }

// -------------- pipelined tf32 GEMM, 3-stage ring (round 11) ----------------
template<int GELU, int MODE, int RESID>
__global__ __launch_bounds__(256, 2) void gemm_pipe(
    const float* __restrict__ A, const float* __restrict__ BT,
    const float* __restrict__ bias, const float* __restrict__ R,
    float* __restrict__ C, int K, int N) {
    extern __shared__ float dsm[];
    int tid  = threadIdx.x;
    int wid  = tid >> 5, lane = tid & 31;
    int g    = lane >> 2, t = lane & 3;
    int m0   = blockIdx.y * 128;
    int n0   = blockIdx.x * 128;
    int wm   = wid >> 1, wn = wid & 1;
    int mbase = wm * 32, nbase = wn * 64;

    const float* Beff = BT;
    if (MODE == 1) Beff = BT + (size_t)((m0 & 1023) >> 2) * K;
    if (MODE == 2) Beff = BT + (size_t)(224 - ((m0 & 1023) >> 2)) * K;

    float acc[2][8][4];
    #pragma unroll
    for (int i = 0; i < 2; i++)
        #pragma unroll
        for (int j = 0; j < 8; j++)
            #pragma unroll
            for (int q = 0; q < 4; q++) acc[i][j][q] = 0.0f;

    int nch = K >> 5;
    #pragma unroll
    for (int s = 0; s < 2; s++) {
        float* sA = dsm + s * STAGEF;
        float* sB = sA + 4608;
        #pragma unroll
        for (int i = 0; i < 4; i++) {
            int idx = tid + i * 256, row = idx >> 3, seg = idx & 7;
            cp16(smem_u32(sA + row * SST + seg * 4),
                 &A[(size_t)(m0 + row) * K + s * 32 + seg * 4]);
            cp16(smem_u32(sB + row * SST + seg * 4),
                 &Beff[(size_t)(n0 + row) * K + s * 32 + seg * 4]);
        }
        CP_COMMIT();
    }

    int stage = 0;
    for (int c = 0; c < nch; c++) {
        CP_WAIT1();
        __syncthreads();
        if (c + 2 < nch) {
            int s = (stage + 2) % NSTAGE;
            float* sA = dsm + s * STAGEF;
            float* sB = sA + 4608;
            #pragma unroll
            for (int i = 0; i < 4; i++) {
                int idx = tid + i * 256, row = idx >> 3, seg = idx & 7;
                cp16(smem_u32(sA + row * SST + seg * 4),
                     &A[(size_t)(m0 + row) * K + (c + 2) * 32 + seg * 4]);
                cp16(smem_u32(sB + row * SST + seg * 4),
                     &Beff[(size_t)(n0 + row) * K + (c + 2) * 32 + seg * 4]);
            }
        }
        CP_COMMIT();
        const uint32_t* sA = (const uint32_t*)(dsm + stage * STAGEF);
        const uint32_t* sB = sA + 4608;
        FRAG_COMPUTE(sA, sB);
        stage = (stage + 1) % NSTAGE;
    }

    #pragma unroll
    for (int mt = 0; mt < 2; mt++) {
        #pragma unroll
        for (int nt = 0; nt < 8; nt++) {
            int col = n0 + nbase + nt * 8 + 2 * t;
            float b0 = bias ? bias[col]     : 0.0f;
            float b1 = bias ? bias[col + 1] : 0.0f;
            int r0 = m0 + mbase + mt * 16 + g;
            int r1 = r0 + 8;
            float v00 = acc[mt][nt][0] + b0, v01 = acc[mt][nt][1] + b1;
            float v10 = acc[mt][nt][2] + b0, v11 = acc[mt][nt][3] + b1;
            if (GELU) {
                v00 = gelu_exact(v00); v01 = gelu_exact(v01);
                v10 = gelu_exact(v10); v11 = gelu_exact(v11);
            }
            if (RESID) {
                float2 x0 = *reinterpret_cast<const float2*>(&R[(size_t)r0 * N + col]);
                float2 x1 = *reinterpret_cast<const float2*>(&R[(size_t)r1 * N + col]);
                v00 += x0.x; v01 += x0.y;
                v10 += x1.x; v11 += x1.y;
            }
            *reinterpret_cast<float2*>(&C[(size_t)r0 * N + col]) = make_float2(v00, v01);
            *reinterpret_cast<float2*>(&C[(size_t)r1 * N + col]) = make_float2(v10, v11);
        }
    }
}

// ------------- fused attention, 512 threads / 16 warps -----------------------
// Phase 1: warp tile 16 l x 128 r (wm=wid>>1 selects 16-row band, wn=wid&1
// selects r half). Phase 2: warp tile 16 l x 64 d. Same smem layout as r11.
#define PST 260
#define VST 132
#define OFF_Q0  0
#define OFF_Q1  4608
#define OFF_K0  9216
#define OFF_K1  18432
#define OFF_P   0
#define OFF_V0  33280
#define OFF_V1  37504
#define OFF_RED 41728
#define FUSED_SMEMF 42240

__global__ __launch_bounds__(512) void fused_attn(
    const float* __restrict__ Q, const float* __restrict__ Km,
    const float* __restrict__ V,
    const float* __restrict__ QD, const float* __restrict__ KD,
    const float* __restrict__ mask, float* __restrict__ CTX) {
    extern __shared__ float dsm[];
    int tid  = threadIdx.x;
    int wid  = tid >> 5, lane = tid & 31;
    int g    = lane >> 2, t = lane & 3;
    int l0   = blockIdx.x * 128;
    int bh   = blockIdx.y;
    int b    = bh >> 2, h = bh & 3;
    int wm   = wid >> 1, wn = wid & 1;
    int mbase = wm * 16;          // 16-row band per warp
    int nbase2 = wn * 64;

    const float* Qb = Q  + (size_t)b * SEQ * DIM + h * DHD;
    const float* Kb = Km + (size_t)b * SEQ * DIM + h * DHD;
    const float* Vb = V  + (size_t)b * SEQ * DIM + h * DHD;

    // ---------------- phase 1: S = Q.K^T (warp: 16 l x 128 r) ---------------
    float acc[16][4];
    #pragma unroll
    for (int j = 0; j < 16; j++)
        #pragma unroll
        for (int q = 0; q < 4; q++) acc[j][q] = 0.0f;

    {
        float* sQ = dsm + OFF_Q0;
        float* sK = dsm + OFF_K0;
        #pragma unroll
        for (int i = 0; i < 2; i++) {
            int idx = tid + i * 512, row = idx >> 3, seg = idx & 7;
            cp16(smem_u32(sQ + row * SST + seg * 4),
                 &Qb[(size_t)(l0 + row) * DIM + seg * 4]);
        }
        #pragma unroll
        for (int i = 0; i < 4; i++) {
            int idx = tid + i * 512, row = idx >> 3, seg = idx & 7;
            cp16(smem_u32(sK + row * SST + seg * 4),
                 &Kb[(size_t)row * DIM + seg * 4]);
        }
        CP_COMMIT();
    }
    for (int c = 0; c < 4; c++) {
        if (c + 1 < 4) {
            float* sQ = dsm + ((c + 1) & 1 ? OFF_Q1 : OFF_Q0);
            float* sK = dsm + ((c + 1) & 1 ? OFF_K1 : OFF_K0);
            #pragma unroll
            for (int i = 0; i < 2; i++) {
                int idx = tid + i * 512, row = idx >> 3, seg = idx & 7;
                cp16(smem_u32(sQ + row * SST + seg * 4),
                     &Qb[(size_t)(l0 + row) * DIM + (c + 1) * 32 + seg * 4]);
            }
            #pragma unroll
            for (int i = 0; i < 4; i++) {
                int idx = tid + i * 512, row = idx >> 3, seg = idx & 7;
                cp16(smem_u32(sK + row * SST + seg * 4),
                     &Kb[(size_t)row * DIM + (c + 1) * 32 + seg * 4]);
            }
            CP_COMMIT();
        } else {
            CP_COMMIT();
        }
        CP_WAIT1();
        __syncthreads();
        const uint32_t* sQ = (const uint32_t*)(dsm + ((c & 1) ? OFF_Q1 : OFF_Q0));
        const uint32_t* sK = (const uint32_t*)(dsm + ((c & 1) ? OFF_K1 : OFF_K0));
        #pragma unroll
        for (int kk = 0; kk < 32; kk += 8) {
            uint32_t af[4];
            {
                int r = mbase + g;
                af[0] = sQ[r * SST + kk + t];
                af[1] = sQ[(r + 8) * SST + kk + t];
                af[2] = sQ[r * SST + kk + t + 4];
                af[3] = sQ[(r + 8) * SST + kk + t + 4];
            }
            #pragma unroll
            for (int nt = 0; nt < 16; nt++) {
                uint32_t bf[2];
                int r = wn * 128 + nt * 8 + g;
                bf[0] = sK[r * SST + kk + t];
                bf[1] = sK[r * SST + kk + t + 4];
                mma_tf32(acc[nt], af, bf);
            }
        }
        __syncthreads();
    }

    // ------------- epilogue: gathers + scale + mask, in place ---------------
    {
        int ll0 = l0 + mbase + g;
        int ll1 = ll0 + 8;
        size_t qdr0 = ((size_t)(b * SEQ + ll0) * NHEAD + h) * QCOLS;
        size_t qdr1 = ((size_t)(b * SEQ + ll1) * NHEAD + h) * QCOLS;
        #pragma unroll
        for (int nt = 0; nt < 16; nt++) {
            int rr0 = wn * 128 + nt * 8 + 2 * t;
            int rr1 = rr0 + 1;
            size_t kdr0 = ((size_t)(b * SEQ + rr0) * NHEAD + h) * QCOLS;
            size_t kdr1 = ((size_t)(b * SEQ + rr1) * NHEAD + h) * QCOLS;
            float bias0 = (1.0f - mask[b * SEQ + rr0]) * (-1e9f);
            float bias1 = (1.0f - mask[b * SEQ + rr1]) * (-1e9f);
            int jq00 = (ll0 & 31) + 255 - rr0, jq01 = jq00 - 1;
            int jq10 = (ll1 & 31) + 255 - rr0, jq11 = jq10 - 1;
            int jk00 = ll0 - (rr0 & 31) + 31,  jk01 = ll0 - (rr1 & 31) + 31;
            int jk10 = ll1 - (rr0 & 31) + 31,  jk11 = ll1 - (rr1 & 31) + 31;
            acc[nt][0] = (acc[nt][0] + QD[qdr0 + jq00] + KD[kdr0 + jk00]) * SM_SCALE + bias0;
            acc[nt][1] = (acc[nt][1] + QD[qdr0 + jq01] + KD[kdr1 + jk01]) * SM_SCALE + bias1;
            acc[nt][2] = (acc[nt][2] + QD[qdr1 + jq10] + KD[kdr0 + jk10]) * SM_SCALE + bias0;
            acc[nt][3] = (acc[nt][3] + QD[qdr1 + jq11] + KD[kdr1 + jk11]) * SM_SCALE + bias1;
        }
    }

    // --------------------------- softmax over r -----------------------------
    float* rmax = dsm + OFF_RED;        // [2][128]
    float* rsum = dsm + OFF_RED + 256;
    float mx[2];
    #pragma unroll
    for (int hf = 0; hf < 2; hf++) {
        float m = -1e30f;
        #pragma unroll
        for (int nt = 0; nt < 16; nt++) {
            m = fmaxf(m, acc[nt][hf * 2]);
            m = fmaxf(m, acc[nt][hf * 2 + 1]);
        }
        m = fmaxf(m, __shfl_xor_sync(0xffffffffu, m, 1));
        m = fmaxf(m, __shfl_xor_sync(0xffffffffu, m, 2));
        mx[hf] = m;
    }
    if (t == 0) {
        #pragma unroll
        for (int hf = 0; hf < 2; hf++) {
            int lrow = mbase + hf * 8 + g;
            rmax[wn * 128 + lrow] = mx[hf];
        }
    }
    __syncthreads();
    #pragma unroll
    for (int hf = 0; hf < 2; hf++) {
        int lrow = mbase + hf * 8 + g;
        float m = fmaxf(rmax[lrow], rmax[128 + lrow]);
        float s = 0.0f;
        #pragma unroll
        for (int nt = 0; nt < 16; nt++) {
            float e0 = __expf(acc[nt][hf * 2]     - m);
            float e1 = __expf(acc[nt][hf * 2 + 1] - m);
            acc[nt][hf * 2]     = e0;
            acc[nt][hf * 2 + 1] = e1;
            s += e0 + e1;
        }
        s += __shfl_xor_sync(0xffffffffu, s, 1);
        s += __shfl_xor_sync(0xffffffffu, s, 2);
        if (t == 0) rsum[wn * 128 + lrow] = s;
    }
    __syncthreads();
    #pragma unroll
    for (int hf = 0; hf < 2; hf++) {
        int lrow = mbase + hf * 8 + g;
        float inv = 1.0f / (rsum[lrow] + rsum[128 + lrow]);
        #pragma unroll
        for (int nt = 0; nt < 16; nt++) {
            acc[nt][hf * 2]     *= inv;
            acc[nt][hf * 2 + 1] *= inv;
        }
    }
    __syncthreads();     // Q/K staging reads done; safe to overwrite with P

    // -------------------------- write P to smem ------------------------------
    float* P = dsm + OFF_P;
    {
        int lr0 = mbase + g;
        int lr1 = lr0 + 8;
        #pragma unroll
        for (int nt = 0; nt < 16; nt++) {
            int col = wn * 128 + nt * 8 + 2 * t;
            *reinterpret_cast<float2*>(&P[lr0 * PST + col]) =
                make_float2(acc[nt][0], acc[nt][1]);
            *reinterpret_cast<float2*>(&P[lr1 * PST + col]) =
                make_float2(acc[nt][2], acc[nt][3]);
        }
    }
    __syncthreads();

    // ------------------- phase 2: ctx = P @ V (k = 256) ----------------------
    float acc2[8][4];
    #pragma unroll
    for (int j = 0; j < 8; j++)
        #pragma unroll
        for (int q = 0; q < 4; q++) acc2[j][q] = 0.0f;

    {
        float* sV = dsm + OFF_V0;
        #pragma unroll
        for (int i = 0; i < 2; i++) {
            int idx = tid + i * 512, r = idx >> 5, dseg = idx & 31;
            cp16(smem_u32(sV + r * VST + dseg * 4),
                 &Vb[(size_t)r * DIM + dseg * 4]);
        }
        CP_COMMIT();
    }
    for (int c = 0; c < 8; c++) {
        if (c + 1 < 8) {
            float* sV = dsm + (((c + 1) & 1) ? OFF_V1 : OFF_V0);
            #pragma unroll
            for (int i = 0; i < 2; i++) {
                int idx = tid + i * 512, r = idx >> 5, dseg = idx & 31;
                cp16(smem_u32(sV + r * VST + dseg * 4),
                     &Vb[(size_t)((c + 1) * 32 + r) * DIM + dseg * 4]);
            }
            CP_COMMIT();
        } else {
            CP_COMMIT();
        }
        CP_WAIT1();
        __syncthreads();
        const uint32_t* sP = (const uint32_t*)P;
        const uint32_t* sV = (const uint32_t*)(dsm + ((c & 1) ? OFF_V1 : OFF_V0));
        #pragma unroll
        for (int kk = 0; kk < 32; kk += 8) {
            uint32_t af[4];
            {
                int r = mbase + g;
                af[0] = sP[r * PST + c * 32 + kk + t];
                af[1] = sP[(r + 8) * PST + c * 32 + kk + t];
                af[2] = sP[r * PST + c * 32 + kk + t + 4];
                af[3] = sP[(r + 8) * PST + c * 32 + kk + t + 4];
            }
            #pragma unroll
            for (int nt = 0; nt < 8; nt++) {
                uint32_t bf[2];
                int d = nbase2 + nt * 8 + g;
                bf[0] = sV[(kk + t) * VST + d];
                bf[1] = sV[(kk + t + 4) * VST + d];
                mma_tf32(acc2[nt], af, bf);
            }
        }
        __syncthreads();
    }

    {
        int rr0 = l0 + mbase + g;
        int rr1 = rr0 + 8;
        #pragma unroll
        for (int nt = 0; nt < 8; nt++) {
            int col = nbase2 + nt * 8 + 2 * t;
            float* dst0 = &CTX[(size_t)(b * SEQ + rr0) * DIM + h * DHD + col];
            float* dst1 = &CTX[(size_t)(b * SEQ + rr1) * DIM + h * DHD + col];
            *reinterpret_cast<float2*>(dst0) = make_float2(acc2[nt][0], acc2[nt][1]);
            *reinterpret_cast<float2*>(dst1) = make_float2(acc2[nt][2], acc2[nt][3]);
        }
    }
}

// ---------------- fused weight prep: all transposes + dist pad --------------
__global__ void wprep(const float* __restrict__ Wq, const float* __restrict__ Wk,
                      const float* __restrict__ Wv, const float* __restrict__ Wo,
                      const float* __restrict__ Wi, const float* __restrict__ Wo2,
                      const float* __restrict__ dist,
                      float* __restrict__ WqT, float* __restrict__ WkT,
                      float* __restrict__ WvT, float* __restrict__ WoT,
                      float* __restrict__ WiT, float* __restrict__ Wo2T,
                      float* __restrict__ dPp) {
    int z = blockIdx.z;
    int i = blockIdx.x * 256 + threadIdx.x;
    if (z < 4) {
        const float* S = (z == 0) ? Wq : (z == 1) ? Wk : (z == 2) ? Wv : Wo;
        float* D       = (z == 0) ? WqT : (z == 1) ? WkT : (z == 2) ? WvT : WoT;
        int l = i >> 18;
        int w = i & 262143;
        int k = w >> 9, n = w & 511;
        D[(size_t)l * 262144 + n * 512 + k] = tf32_rna(S[i]);
    } else if (z == 4) {
        if (i < LNUM * DIM * FFI) {
            int l = i >> 16, w = i & 65535;
            int k = w >> 7, n = w & 127;
            WiT[(size_t)l * 65536 + n * 512 + k] = tf32_rna(Wi[i]);
        }
    } else if (z == 5) {
        if (i < LNUM * FFI * DIM) {
            int l = i >> 16, w = i & 65535;
            int k = w >> 9, n = w & 511;
            Wo2T[(size_t)l * 65536 + n * 128 + k] = tf32_rna(Wo2[i]);
        }
    } else {
        if (i < DPAD * DHD) {
            int pp = i >> 7;
            dPp[i] = (pp < 511) ? tf32_rna(dist[i]) : 0.0f;
        }
    }
}

// --------------------------- embedding + LN ---------------------------------
__device__ __forceinline__ void block_reduce2(float& a, float& b) {
    __shared__ float sa[8], sb[8];
    int lane = threadIdx.x & 31, w = threadIdx.x >> 5;
    #pragma unroll
    for (int o = 16; o; o >>= 1) {
        a += __shfl_xor_sync(0xffffffffu, a, o);
        b += __shfl_xor_sync(0xffffffffu, b, o);
    }
    if (lane == 0) { sa[w] = a; sb[w] = b; }
    __syncthreads();
    if (w == 0) {
        a = (lane < 8) ? sa[lane] : 0.0f;
        b = (lane < 8) ? sb[lane] : 0.0f;
        #pragma unroll
        for (int o = 4; o; o >>= 1) {
            a += __shfl_xor_sync(0xffffffffu, a, o);
            b += __shfl_xor_sync(0xffffffffu, b, o);
        }
        if (lane == 0) { sa[0] = a; sb[0] = b; }
    }
    __syncthreads();
    a = sa[0]; b = sb[0];
}

__global__ void embed_ln(const int* __restrict__ ids, const float* __restrict__ inW,
                         const float* __restrict__ inb, const float* __restrict__ tok,
                         const float* __restrict__ g,  const float* __restrict__ bb,
                         float* __restrict__ X) {
    int tt = blockIdx.x, tid = threadIdx.x;
    float f[NFEAT];
    #pragma unroll
    for (int i = 0; i < NFEAT; i++) f[i] = (float)ids[tt * NFEAT + i];
    int d0 = tid, d1 = tid + 256;
    float v0 = inb[d0] + tok[d0];
    float v1 = inb[d1] + tok[d1];
    #pragma unroll
    for (int i = 0; i < NFEAT; i++) {
        v0 += f[i] * inW[i * DIM + d0];
        v1 += f[i] * inW[i * DIM + d1];
    }
    float s = v0 + v1, q = v0 * v0 + v1 * v1;
    block_reduce2(s, q);
    float mu  = s * (1.0f / DIM);
    float var = q * (1.0f / DIM) - mu * mu;
    float r   = rsqrtf(var + 1e-12f);
    size_t base = (size_t)tt * DIM;
    X[base + d0] = (v0 - mu) * r * g[d0] + bb[d0];
    X[base + d1] = (v1 - mu) * r * g[d1] + bb[d1];
}

// warp-per-token pure LayerNorm
__global__ __launch_bounds__(256) void ln_w(
    const float* __restrict__ in,
    const float* __restrict__ g, const float* __restrict__ bb,
    float* __restrict__ out) {
    int wid = threadIdx.x >> 5, lane = threadIdx.x & 31;
    int tt = blockIdx.x * 8 + wid;
    size_t base = (size_t)tt * DIM;
    float4 v[4];
    float s = 0.0f, q = 0.0f;
    #pragma unroll
    for (int i = 0; i < 4; i++) {
        int col = i * 128 + lane * 4;
        v[i] = *reinterpret_cast<const float4*>(&in[base + col]);
        s += v[i].x + v[i].y + v[i].z + v[i].w;
        q += v[i].x * v[i].x + v[i].y * v[i].y + v[i].z * v[i].z + v[i].w * v[i].w;
    }
    #pragma unroll
    for (int o = 16; o; o >>= 1) {
        s += __shfl_xor_sync(0xffffffffu, s, o);
        q += __shfl_xor_sync(0xffffffffu, q, o);
    }
    float mu  = s * (1.0f / DIM);
    float var = q * (1.0f / DIM) - mu * mu;
    float r   = rsqrtf(var + 1e-12f);
    #pragma unroll
    for (int i = 0; i < 4; i++) {
        int col = i * 128 + lane * 4;
        float4 g4 = *reinterpret_cast<const float4*>(&g[col]);
        float4 b4 = *reinterpret_cast<const float4*>(&bb[col]);
        float4 o4;
        o4.x = (v[i].x - mu) * r * g4.x + b4.x;
        o4.y = (v[i].y - mu) * r * g4.y + b4.y;
        o4.z = (v[i].z - mu) * r * g4.z + b4.z;
        o4.w = (v[i].w - mu) * r * g4.w + b4.w;
        *reinterpret_cast<float4*>(&out[base + col]) = o4;
    }
}

// ------------------------------ host driver ----------------------------------
extern "C" void kernel_launch(void* const* d_in, const int* in_sizes, int n_in,
                              void* d_out, int out_size) {
    (void)in_sizes; (void)n_in; (void)out_size;
    const int*   ids  = (const int*)  d_in[0];
    const float* mask = (const float*)d_in[1];
    const float* inW  = (const float*)d_in[2];
    const float* inb  = (const float*)d_in[3];
    const float* tok  = (const float*)d_in[4];
    const float* elg  = (const float*)d_in[5];
    const float* elb  = (const float*)d_in[6];
    const float* dist = (const float*)d_in[7];
    const float* Wq   = (const float*)d_in[8];
    const float* bq   = (const float*)d_in[9];
    const float* Wk   = (const float*)d_in[10];
    const float* bk   = (const float*)d_in[11];
    const float* Wv   = (const float*)d_in[12];
    const float* bv   = (const float*)d_in[13];
    const float* Wo   = (const float*)d_in[14];
    const float* bo   = (const float*)d_in[15];
    const float* ln1g = (const float*)d_in[16];
    const float* ln1b = (const float*)d_in[17];
    const float* Wi   = (const float*)d_in[18];
    const float* bi   = (const float*)d_in[19];
    const float* Wo2  = (const float*)d_in[20];
    const float* bo2  = (const float*)d_in[21];
    const float* ln2g = (const float*)d_in[22];
    const float* ln2b = (const float*)d_in[23];
    float* out = (float*)d_out;

    float *X, *Q, *Kb, *V, *CTX, *TMP, *Hb, *QD, *KD, *dP;
    float *WqT, *WkT, *WvT, *WoT, *WiT, *Wo2T;
    cudaGetSymbolAddress((void**)&X,    g_X);
    cudaGetSymbolAddress((void**)&Q,    g_Q);
    cudaGetSymbolAddress((void**)&Kb,   g_K);
    cudaGetSymbolAddress((void**)&V,    g_V);
    cudaGetSymbolAddress((void**)&CTX,  g_CTX);
    cudaGetSymbolAddress((void**)&TMP,  g_TMP);
    cudaGetSymbolAddress((void**)&Hb,   g_Hb);
    cudaGetSymbolAddress((void**)&QD,   g_QD);
    cudaGetSymbolAddress((void**)&KD,   g_KD);
    cudaGetSymbolAddress((void**)&dP,   g_dP);
    cudaGetSymbolAddress((void**)&WqT,  g_WqT);
    cudaGetSymbolAddress((void**)&WkT,  g_WkT);
    cudaGetSymbolAddress((void**)&WvT,  g_WvT);
    cudaGetSymbolAddress((void**)&WoT,  g_WoT);
    cudaGetSymbolAddress((void**)&WiT,  g_WiT);
    cudaGetSymbolAddress((void**)&Wo2T, g_Wo2T);

    const int GEMM_SMEM  = NSTAGE * STAGEF * 4;
    const int FUSED_SMEM = FUSED_SMEMF * 4;
    cudaFuncSetAttribute(gemm_pipe<0,0,0>, cudaFuncAttributeMaxDynamicSharedMemorySize, GEMM_SMEM);
    cudaFuncSetAttribute(gemm_pipe<0,1,0>, cudaFuncAttributeMaxDynamicSharedMemorySize, GEMM_SMEM);
    cudaFuncSetAttribute(gemm_pipe<0,2,0>, cudaFuncAttributeMaxDynamicSharedMemorySize, GEMM_SMEM);
    cudaFuncSetAttribute(gemm_pipe<0,0,1>, cudaFuncAttributeMaxDynamicSharedMemorySize, GEMM_SMEM);
    cudaFuncSetAttribute(gemm_pipe<1,0,0>, cudaFuncAttributeMaxDynamicSharedMemorySize, GEMM_SMEM);
    cudaFuncSetAttribute(fused_attn,       cudaFuncAttributeMaxDynamicSharedMemorySize, FUSED_SMEM);

    wprep<<<dim3(4096, 1, 7), 256>>>(Wq, Wk, Wv, Wo, Wi, Wo2, dist,
                                     WqT, WkT, WvT, WoT, WiT, Wo2T, dP);
    embed_ln<<<TOK, 256>>>(ids, inW, inb, tok, elg, elb, X);

    dim3 gG(DIM / 128, TOK / 128);
    dim3 gGi(FFI / 128, TOK / 128);
    dim3 gQD(QCOLS / 128, ROWSBH / 128);
    dim3 gA(SEQ / 128, BATCH * NHEAD);

    for (int l = 0; l < LNUM; l++) {
        const float* wqt  = WqT  + (size_t)l * DIM * DIM;
        const float* wkt  = WkT  + (size_t)l * DIM * DIM;
        const float* wvt  = WvT  + (size_t)l * DIM * DIM;
        const float* wot  = WoT  + (size_t)l * DIM * DIM;
        const float* wit  = WiT  + (size_t)l * FFI * DIM;
        const float* wo2t = Wo2T + (size_t)l * DIM * FFI;

        gemm_pipe<0,0,0><<<gG, 256, GEMM_SMEM>>>(X, wqt, bq + l * DIM, nullptr, Q,  DIM, DIM);
        gemm_pipe<0,0,0><<<gG, 256, GEMM_SMEM>>>(X, wkt, bk + l * DIM, nullptr, Kb, DIM, DIM);
        gemm_pipe<0,0,0><<<gG, 256, GEMM_SMEM>>>(X, wvt, bv + l * DIM, nullptr, V,  DIM, DIM);

        gemm_pipe<0,1,0><<<gQD, 256, GEMM_SMEM>>>(Q,  dP, nullptr, nullptr, QD, DHD, QCOLS);
        gemm_pipe<0,2,0><<<gQD, 256, GEMM_SMEM>>>(Kb, dP, nullptr, nullptr, KD, DHD, QCOLS);

        fused_attn<<<gA, 512, FUSED_SMEM>>>(Q, Kb, V, QD, KD, mask, CTX);

        gemm_pipe<0,0,1><<<gG, 256, GEMM_SMEM>>>(CTX, wot, bo + l * DIM, X, TMP, DIM, DIM);
        ln_w<<<TOK / 8, 256>>>(TMP, ln1g + l * DIM, ln1b + l * DIM, X);

        gemm_pipe<1,0,0><<<gGi, 256, GEMM_SMEM>>>(X, wit, bi + l * FFI, nullptr, Hb, DIM, FFI);
        gemm_pipe<0,0,1><<<gG, 256, GEMM_SMEM>>>(Hb, wo2t, bo2 + l * DIM, X, TMP, FFI, DIM);
        ln_w<<<TOK / 8, 256>>>(TMP, ln2g + l * DIM, ln2b + l * DIM,
                               (l == LNUM - 1) ? out : X);
    }
}

// round 14
// speedup vs baseline: 1.5793x; 1.5793x over previous
#include <cuda_runtime.h>
#include <math.h>
#include <stdint.h>

// ---------------------------------------------------------------------------
// ExpressionBert forward. tf32 mma.sync + cp.async pipelines.
// Round 14: base = round 11 (best). fused_attn reverted to 256-thread r11
// version. QKV batched into one z=3 launch, QD/KD into one z=2 launch using
// contiguous buffers + scalar z-selects (no structs, no register bloat).
// ---------------------------------------------------------------------------

#define LNUM   4
#define DIM    512
#define NHEAD  4
#define DHD    128
#define FFI    128
#define SEQ    256
#define BATCH  128
#define NFEAT  6
#define TOK    (BATCH*SEQ)          // 32768
#define ROWSBH (BATCH*NHEAD*SEQ)    // 131072
#define QCOLS  384
#define DPAD   608

#define SM_SCALE 0.08838834764831845f  // 1/sqrt(128)

// ------------------------- static device scratch ---------------------------
__device__ float g_X   [TOK*DIM];
__device__ float g_QKV [(size_t)3*TOK*DIM];          // Q | K | V contiguous
__device__ float g_CTX [TOK*DIM];
__device__ float g_TMP [TOK*DIM];
__device__ float g_Hb  [TOK*FFI];
__device__ float g_QDKD[(size_t)2*ROWSBH*QCOLS];     // QD | KD contiguous
__device__ float g_dP  [DPAD*DHD];

__device__ float g_WqkvT[(size_t)3*LNUM*DIM*DIM];    // WqT | WkT | WvT
__device__ float g_WoT  [LNUM*DIM*DIM];
__device__ float g_WiT  [LNUM*FFI*DIM];
__device__ float g_Wo2T [LNUM*DIM*FFI];

// ------------------------------ helpers -------------------------------------
__device__ __forceinline__ uint32_t smem_u32(const void* p) {
    uint32_t a;
    asm("{ .reg .u64 t; cvta.to.shared.u64 t, %1; cvt.u32.u64 %0, t; }"
        : "=r"(a) : "l"(p));
    return a;
}

__device__ __forceinline__ float gelu_exact(float x) {
    return 0.5f * x * (1.0f + erff(x * 0.70710678118654752440f));
}

__device__ __forceinline__ float tf32_rna(float f) {
    uint32_t u;
    asm("cvt.rna.tf32.f32 %0, %1;" : "=r"(u) : "f"(f));
    return __uint_as_float(u);
}

__device__ __forceinline__ void mma_tf32(float* d, const uint32_t* a,
                                         const uint32_t* b) {
    asm volatile(
        "mma.sync.aligned.m16n8k8.row.col.f32.tf32.tf32.f32 "
        "{%0,%1,%2,%3}, {%4,%5,%6,%7}, {%8,%9}, {%0,%1,%2,%3};"
        : "+f"(d[0]), "+f"(d[1]), "+f"(d[2]), "+f"(d[3])
        : "r"(a[0]), "r"(a[1]), "r"(a[2]), "r"(a[3]), "r"(b[0]), "r"(b[1]));
}

__device__ __forceinline__ void cp16(uint32_t saddr, const void* gptr) {
    asm volatile("cp.async.cg.shared.global [%0], [%1], 16;"
                 :: "r"(saddr), "l"(gptr) : "memory");
}
#define CP_COMMIT() asm volatile("cp.async.commit_group;" ::: "memory")
#define CP_WAIT1()  asm volatile("cp.async.wait_group 1;" ::: "memory")

#define SST 36
#define STAGEF 9216
#define NSTAGE 3

#define FRAG_COMPUTE(sA, sB)                                                   \
    _Pragma("unroll")                                                          \
    for (int kk = 0; kk < 32; kk += 8) {                                       \
        uint32_t af[2][4];                                                     \
        _Pragma("unroll")                                                      \
        for (int mt = 0; mt < 2; mt++) {                                       \
            int r = mbase + mt * 16 + g;                                       \
            af[mt][0] = (sA)[r * SST + kk + t];                                \
            af[mt][1] = (sA)[(r + 8) * SST + kk + t];                          \
            af[mt][2] = (sA)[r * SST + kk + t + 4];                            \
            af[mt][3] = (sA)[(r + 8) * SST + kk + t + 4];                      \
        }                                                                      \
        uint32_t bf[8][2];                                                     \
        _Pragma("unroll")                                                      \
        for (int nt = 0; nt < 8; nt++) {                                       \
            int r = nbase + nt * 8 + g;                                        \
            bf[nt][0] = (sB)[r * SST + kk + t];                                \
            bf[nt][1] = (sB)[r * SST + kk + t + 4];                            \
        }                                                                      \
        _Pragma("unroll")                                                      \
        for (int mt = 0; mt < 2; mt++)                                         \
            _Pragma("unroll")                                                  \
            for (int nt = 0; nt < 8; nt++)                                     \
                mma_tf32(acc[mt][nt], af[mt], bf[nt]);                         \
    }

// main-loop body shared by all GEMM kernels (3-stage ring, 1 sync/chunk)
#define GEMM_MAINLOOP(Aptr, Bptr, Kdim)                                        \
    int nch = (Kdim) >> 5;                                                     \
    _Pragma("unroll")                                                          \
    for (int s = 0; s < 2; s++) {                                              \
        float* sA = dsm + s * STAGEF;                                          \
        float* sB = sA + 4608;                                                 \
        _Pragma("unroll")                                                      \
        for (int i = 0; i < 4; i++) {                                          \
            int idx = tid + i * 256, row = idx >> 3, seg = idx & 7;            \
            cp16(smem_u32(sA + row * SST + seg * 4),                           \
                 &(Aptr)[(size_t)(m0 + row) * (Kdim) + s * 32 + seg * 4]);     \
            cp16(smem_u32(sB + row * SST + seg * 4),                           \
                 &(Bptr)[(size_t)(n0 + row) * (Kdim) + s * 32 + seg * 4]);     \
        }                                                                      \
        CP_COMMIT();                                                           \
    }                                                                          \
    int stage = 0;                                                             \
    for (int c = 0; c < nch; c++) {                                            \
        CP_WAIT1();                                                            \
        __syncthreads();                                                       \
        if (c + 2 < nch) {                                                     \
            int s = (stage + 2) % NSTAGE;                                      \
            float* sA = dsm + s * STAGEF;                                      \
            float* sB = sA + 4608;                                             \
            _Pragma("unroll")                                                  \
            for (int i = 0; i < 4; i++) {                                      \
                int idx = tid + i * 256, row = idx >> 3, seg = idx & 7;        \
                cp16(smem_u32(sA + row * SST + seg * 4),                       \
                     &(Aptr)[(size_t)(m0 + row) * (Kdim) + (c + 2) * 32 + seg * 4]); \
                cp16(smem_u32(sB + row * SST + seg * 4),                       \
                     &(Bptr)[(size_t)(n0 + row) * (Kdim) + (c + 2) * 32 + seg * 4]); \
            }                                                                  \
        }                                                                      \
        CP_COMMIT();                                                           \
        const uint32_t* sA = (const uint32_t*)(dsm + stage * STAGEF);          \
        const uint32_t* sB = sA + 4608;                                        \
        FRAG_COMPUTE(sA, sB);                                                  \
        stage = (stage + 1) % NSTAGE;                                          \
    }

// ---------------- plain pipelined tf32 GEMM (Wo / FFN paths) ----------------
template<int GELU, int RESID>
__global__ __launch_bounds__(256, 2) void gemm_pipe(
    const float* __restrict__ A, const float* __restrict__ BT,
    const float* __restrict__ bias, const float* __restrict__ R,
    float* __restrict__ C, int K, int N) {
    extern __shared__ float dsm[];
    int tid  = threadIdx.x;
    int wid  = tid >> 5, lane = tid & 31;
    int g    = lane >> 2, t = lane & 3;
    int m0   = blockIdx.y * 128;
    int n0   = blockIdx.x * 128;
    int wm   = wid >> 1, wn = wid & 1;
    int mbase = wm * 32, nbase = wn * 64;

    float acc[2][8][4];
    #pragma unroll
    for (int i = 0; i < 2; i++)
        #pragma unroll
        for (int j = 0; j < 8; j++)
            #pragma unroll
            for (int q = 0; q < 4; q++) acc[i][j][q] = 0.0f;

    GEMM_MAINLOOP(A, BT, K)

    #pragma unroll
    for (int mt = 0; mt < 2; mt++) {
        #pragma unroll
        for (int nt = 0; nt < 8; nt++) {
            int col = n0 + nbase + nt * 8 + 2 * t;
            float b0 = bias ? bias[col]     : 0.0f;
            float b1 = bias ? bias[col + 1] : 0.0f;
            int r0 = m0 + mbase + mt * 16 + g;
            int r1 = r0 + 8;
            float v00 = acc[mt][nt][0] + b0, v01 = acc[mt][nt][1] + b1;
            float v10 = acc[mt][nt][2] + b0, v11 = acc[mt][nt][3] + b1;
            if (GELU) {
                v00 = gelu_exact(v00); v01 = gelu_exact(v01);
                v10 = gelu_exact(v10); v11 = gelu_exact(v11);
            }
            if (RESID) {
                float2 x0 = *reinterpret_cast<const float2*>(&R[(size_t)r0 * N + col]);
                float2 x1 = *reinterpret_cast<const float2*>(&R[(size_t)r1 * N + col]);
                v00 += x0.x; v01 += x0.y;
                v10 += x1.x; v11 += x1.y;
            }
            *reinterpret_cast<float2*>(&C[(size_t)r0 * N + col]) = make_float2(v00, v01);
            *reinterpret_cast<float2*>(&C[(size_t)r1 * N + col]) = make_float2(v10, v11);
        }
    }
}

// ---------------- batched QKV GEMM: z selects weight slab / bias / output ----
__global__ __launch_bounds__(256, 2) void gemm_qkv(
    const float* __restrict__ X, const float* __restrict__ Wbase,
    const float* __restrict__ b0p, const float* __restrict__ b1p,
    const float* __restrict__ b2p, float* __restrict__ QKV) {
    extern __shared__ float dsm[];
    int tid  = threadIdx.x;
    int wid  = tid >> 5, lane = tid & 31;
    int g    = lane >> 2, t = lane & 3;
    int m0   = blockIdx.y * 128;
    int n0   = blockIdx.x * 128;
    int z    = blockIdx.z;
    int wm   = wid >> 1, wn = wid & 1;
    int mbase = wm * 32, nbase = wn * 64;

    const float* BT   = Wbase + (size_t)z * (LNUM * DIM * DIM);
    const float* bias = (z == 0) ? b0p : (z == 1) ? b1p : b2p;
    float*       C    = QKV + (size_t)z * (TOK * DIM);

    float acc[2][8][4];
    #pragma unroll
    for (int i = 0; i < 2; i++)
        #pragma unroll
        for (int j = 0; j < 8; j++)
            #pragma unroll
            for (int q = 0; q < 4; q++) acc[i][j][q] = 0.0f;

    GEMM_MAINLOOP(X, BT, DIM)

    #pragma unroll
    for (int mt = 0; mt < 2; mt++) {
        #pragma unroll
        for (int nt = 0; nt < 8; nt++) {
            int col = n0 + nbase + nt * 8 + 2 * t;
            float b0 = bias[col], b1 = bias[col + 1];
            int r0 = m0 + mbase + mt * 16 + g;
            int r1 = r0 + 8;
            *reinterpret_cast<float2*>(&C[(size_t)r0 * DIM + col]) =
                make_float2(acc[mt][nt][0] + b0, acc[mt][nt][1] + b1);
            *reinterpret_cast<float2*>(&C[(size_t)r1 * DIM + col]) =
                make_float2(acc[mt][nt][2] + b0, acc[mt][nt][3] + b1);
        }
    }
}

// ---------------- batched QD/KD GEMM: z selects A / window / output ----------
__global__ __launch_bounds__(256, 2) void gemm_qd(
    const float* __restrict__ QKV, const float* __restrict__ dPp,
    float* __restrict__ QDKD) {
    extern __shared__ float dsm[];
    int tid  = threadIdx.x;
    int wid  = tid >> 5, lane = tid & 31;
    int g    = lane >> 2, t = lane & 3;
    int m0   = blockIdx.y * 128;
    int n0   = blockIdx.x * 128;
    int z    = blockIdx.z;
    int wm   = wid >> 1, wn = wid & 1;
    int mbase = wm * 32, nbase = wn * 64;

    const float* A = QKV + (size_t)z * (TOK * DIM);   // z=0 Q, z=1 K
    float*       C = QDKD + (size_t)z * ((size_t)ROWSBH * QCOLS);
    int s0   = (m0 & 1023) >> 2;
    int woff = z ? (224 - s0) : s0;
    const float* BT = dPp + (size_t)woff * DHD;

    float acc[2][8][4];
    #pragma unroll
    for (int i = 0; i < 2; i++)
        #pragma unroll
        for (int j = 0; j < 8; j++)
            #pragma unroll
            for (int q = 0; q < 4; q++) acc[i][j][q] = 0.0f;

    GEMM_MAINLOOP(A, BT, DHD)

    #pragma unroll
    for (int mt = 0; mt < 2; mt++) {
        #pragma unroll
        for (int nt = 0; nt < 8; nt++) {
            int col = n0 + nbase + nt * 8 + 2 * t;
            int r0 = m0 + mbase + mt * 16 + g;
            int r1 = r0 + 8;
            *reinterpret_cast<float2*>(&C[(size_t)r0 * QCOLS + col]) =
                make_float2(acc[mt][nt][0], acc[mt][nt][1]);
            *reinterpret_cast<float2*>(&C[(size_t)r1 * QCOLS + col]) =
                make_float2(acc[mt][nt][2], acc[mt][nt][3]);
        }
    }
}

// ------------- fused attention: scores + softmax + ctx (r11, 256 thr) -------
#define PST 260
#define VST 132
#define OFF_Q0  0
#define OFF_Q1  4608
#define OFF_K0  9216
#define OFF_K1  18432
#define OFF_P   0
#define OFF_V0  33280
#define OFF_V1  37504
#define OFF_RED 41728
#define FUSED_SMEMF 42240

__global__ __launch_bounds__(256) void fused_attn(
    const float* __restrict__ QKV,
    const float* __restrict__ QDKD,
    const float* __restrict__ mask, float* __restrict__ CTX) {
    extern __shared__ float dsm[];
    int tid  = threadIdx.x;
    int wid  = tid >> 5, lane = tid & 31;
    int g    = lane >> 2, t = lane & 3;
    int l0   = blockIdx.x * 128;
    int bh   = blockIdx.y;
    int b    = bh >> 2, h = bh & 3;
    int wm   = wid >> 1, wn = wid & 1;
    int mbase = wm * 32;
    int nbase2 = wn * 64;

    const float* Qb = QKV + (size_t)b * SEQ * DIM + h * DHD;
    const float* Kb = Qb + (size_t)TOK * DIM;
    const float* Vb = Qb + (size_t)2 * TOK * DIM;
    const float* QD = QDKD;
    const float* KD = QDKD + (size_t)ROWSBH * QCOLS;

    float acc[2][16][4];
    #pragma unroll
    for (int i = 0; i < 2; i++)
        #pragma unroll
        for (int j = 0; j < 16; j++)
            #pragma unroll
            for (int q = 0; q < 4; q++) acc[i][j][q] = 0.0f;

    {
        float* sQ = dsm + OFF_Q0;
        float* sK = dsm + OFF_K0;
        #pragma unroll
        for (int i = 0; i < 4; i++) {
            int idx = tid + i * 256, row = idx >> 3, seg = idx & 7;
            cp16(smem_u32(sQ + row * SST + seg * 4),
                 &Qb[(size_t)(l0 + row) * DIM + seg * 4]);
        }
        #pragma unroll
        for (int i = 0; i < 8; i++) {
            int idx = tid + i * 256, row = idx >> 3, seg = idx & 7;
            cp16(smem_u32(sK + row * SST + seg * 4),
                 &Kb[(size_t)row * DIM + seg * 4]);
        }
        CP_COMMIT();
    }
    for (int c = 0; c < 4; c++) {
        if (c + 1 < 4) {
            float* sQ = dsm + ((c + 1) & 1 ? OFF_Q1 : OFF_Q0);
            float* sK = dsm + ((c + 1) & 1 ? OFF_K1 : OFF_K0);
            #pragma unroll
            for (int i = 0; i < 4; i++) {
                int idx = tid + i * 256, row = idx >> 3, seg = idx & 7;
                cp16(smem_u32(sQ + row * SST + seg * 4),
                     &Qb[(size_t)(l0 + row) * DIM + (c + 1) * 32 + seg * 4]);
            }
            #pragma unroll
            for (int i = 0; i < 8; i++) {
                int idx = tid + i * 256, row = idx >> 3, seg = idx & 7;
                cp16(smem_u32(sK + row * SST + seg * 4),
                     &Kb[(size_t)row * DIM + (c + 1) * 32 + seg * 4]);
            }
            CP_COMMIT();
        } else {
            CP_COMMIT();
        }
        CP_WAIT1();
        __syncthreads();
        const uint32_t* sQ = (const uint32_t*)(dsm + ((c & 1) ? OFF_Q1 : OFF_Q0));
        const uint32_t* sK = (const uint32_t*)(dsm + ((c & 1) ? OFF_K1 : OFF_K0));
        #pragma unroll
        for (int kk = 0; kk < 32; kk += 8) {
            uint32_t af[2][4];
            #pragma unroll
            for (int mt = 0; mt < 2; mt++) {
                int r = mbase + mt * 16 + g;
                af[mt][0] = sQ[r * SST + kk + t];
                af[mt][1] = sQ[(r + 8) * SST + kk + t];
                af[mt][2] = sQ[r * SST + kk + t + 4];
                af[mt][3] = sQ[(r + 8) * SST + kk + t + 4];
            }
            #pragma unroll
            for (int nth = 0; nth < 2; nth++) {
                uint32_t bf[8][2];
                #pragma unroll
                for (int j = 0; j < 8; j++) {
                    int r = wn * 128 + nth * 64 + j * 8 + g;
                    bf[j][0] = sK[r * SST + kk + t];
                    bf[j][1] = sK[r * SST + kk + t + 4];
                }
                #pragma unroll
                for (int mt = 0; mt < 2; mt++)
                    #pragma unroll
                    for (int j = 0; j < 8; j++)
                        mma_tf32(acc[mt][nth * 8 + j], af[mt], bf[j]);
            }
        }
        __syncthreads();
    }

    #pragma unroll
    for (int mt = 0; mt < 2; mt++) {
        int ll0 = l0 + mbase + mt * 16 + g;
        int ll1 = ll0 + 8;
        size_t qdr0 = ((size_t)(b * SEQ + ll0) * NHEAD + h) * QCOLS;
        size_t qdr1 = ((size_t)(b * SEQ + ll1) * NHEAD + h) * QCOLS;
        #pragma unroll
        for (int nt = 0; nt < 16; nt++) {
            int rr0 = wn * 128 + nt * 8 + 2 * t;
            int rr1 = rr0 + 1;
            size_t kdr0 = ((size_t)(b * SEQ + rr0) * NHEAD + h) * QCOLS;
            size_t kdr1 = ((size_t)(b * SEQ + rr1) * NHEAD + h) * QCOLS;
            float bias0 = (1.0f - mask[b * SEQ + rr0]) * (-1e9f);
            float bias1 = (1.0f - mask[b * SEQ + rr1]) * (-1e9f);
            int jq00 = (ll0 & 31) + 255 - rr0, jq01 = jq00 - 1;
            int jq10 = (ll1 & 31) + 255 - rr0, jq11 = jq10 - 1;
            int jk00 = ll0 - (rr0 & 31) + 31,  jk01 = ll0 - (rr1 & 31) + 31;
            int jk10 = ll1 - (rr0 & 31) + 31,  jk11 = ll1 - (rr1 & 31) + 31;
            acc[mt][nt][0] = (acc[mt][nt][0] + QD[qdr0 + jq00] + KD[kdr0 + jk00]) * SM_SCALE + bias0;
            acc[mt][nt][1] = (acc[mt][nt][1] + QD[qdr0 + jq01] + KD[kdr1 + jk01]) * SM_SCALE + bias1;
            acc[mt][nt][2] = (acc[mt][nt][2] + QD[qdr1 + jq10] + KD[kdr0 + jk10]) * SM_SCALE + bias0;
            acc[mt][nt][3] = (acc[mt][nt][3] + QD[qdr1 + jq11] + KD[kdr1 + jk11]) * SM_SCALE + bias1;
        }
    }

    float* rmax = dsm + OFF_RED;
    float* rsum = dsm + OFF_RED + 256;
    float mx[2][2];
    #pragma unroll
    for (int mt = 0; mt < 2; mt++)
        #pragma unroll
        for (int hf = 0; hf < 2; hf++) {
            float m = -1e30f;
            #pragma unroll
            for (int nt = 0; nt < 16; nt++) {
                m = fmaxf(m, acc[mt][nt][hf * 2]);
                m = fmaxf(m, acc[mt][nt][hf * 2 + 1]);
            }
            m = fmaxf(m, __shfl_xor_sync(0xffffffffu, m, 1));
            m = fmaxf(m, __shfl_xor_sync(0xffffffffu, m, 2));
            mx[mt][hf] = m;
        }
    if (t == 0) {
        #pragma unroll
        for (int mt = 0; mt < 2; mt++)
            #pragma unroll
            for (int hf = 0; hf < 2; hf++) {
                int lrow = mbase + mt * 16 + hf * 8 + g;
                rmax[wn * 128 + lrow] = mx[mt][hf];
            }
    }
    __syncthreads();
    #pragma unroll
    for (int mt = 0; mt < 2; mt++)
        #pragma unroll
        for (int hf = 0; hf < 2; hf++) {
            int lrow = mbase + mt * 16 + hf * 8 + g;
            float m = fmaxf(rmax[lrow], rmax[128 + lrow]);
            float s = 0.0f;
            #pragma unroll
            for (int nt = 0; nt < 16; nt++) {
                float e0 = __expf(acc[mt][nt][hf * 2]     - m);
                float e1 = __expf(acc[mt][nt][hf * 2 + 1] - m);
                acc[mt][nt][hf * 2]     = e0;
                acc[mt][nt][hf * 2 + 1] = e1;
                s += e0 + e1;
            }
            s += __shfl_xor_sync(0xffffffffu, s, 1);
            s += __shfl_xor_sync(0xffffffffu, s, 2);
            if (t == 0) rsum[wn * 128 + lrow] = s;
        }
    __syncthreads();
    #pragma unroll
    for (int mt = 0; mt < 2; mt++)
        #pragma unroll
        for (int hf = 0; hf < 2; hf++) {
            int lrow = mbase + mt * 16 + hf * 8 + g;
            float inv = 1.0f / (rsum[lrow] + rsum[128 + lrow]);
            #pragma unroll
            for (int nt = 0; nt < 16; nt++) {
                acc[mt][nt][hf * 2]     *= inv;
                acc[mt][nt][hf * 2 + 1] *= inv;
            }
        }
    __syncthreads();

    float* P = dsm + OFF_P;
    #pragma unroll
    for (int mt = 0; mt < 2; mt++) {
        int lr0 = mbase + mt * 16 + g;
        int lr1 = lr0 + 8;
        #pragma unroll
        for (int nt = 0; nt < 16; nt++) {
            int col = wn * 128 + nt * 8 + 2 * t;
            *reinterpret_cast<float2*>(&P[lr0 * PST + col]) =
                make_float2(acc[mt][nt][0], acc[mt][nt][1]);
            *reinterpret_cast<float2*>(&P[lr1 * PST + col]) =
                make_float2(acc[mt][nt][2], acc[mt][nt][3]);
        }
    }
    __syncthreads();

    float acc2[2][8][4];
    #pragma unroll
    for (int i = 0; i < 2; i++)
        #pragma unroll
        for (int j = 0; j < 8; j++)
            #pragma unroll
            for (int q = 0; q < 4; q++) acc2[i][j][q] = 0.0f;

    {
        float* sV = dsm + OFF_V0;
        #pragma unroll
        for (int i = 0; i < 4; i++) {
            int idx = tid + i * 256, r = idx >> 5, dseg = idx & 31;
            cp16(smem_u32(sV + r * VST + dseg * 4),
                 &Vb[(size_t)r * DIM + dseg * 4]);
        }
        CP_COMMIT();
    }
    for (int c = 0; c < 8; c++) {
        if (c + 1 < 8) {
            float* sV = dsm + (((c + 1) & 1) ? OFF_V1 : OFF_V0);
            #pragma unroll
            for (int i = 0; i < 4; i++) {
                int idx = tid + i * 256, r = idx >> 5, dseg = idx & 31;
                cp16(smem_u32(sV + r * VST + dseg * 4),
                     &Vb[(size_t)((c + 1) * 32 + r) * DIM + dseg * 4]);
            }
            CP_COMMIT();
        } else {
            CP_COMMIT();
        }
        CP_WAIT1();
        __syncthreads();
        const uint32_t* sP = (const uint32_t*)P;
        const uint32_t* sV = (const uint32_t*)(dsm + ((c & 1) ? OFF_V1 : OFF_V0));
        #pragma unroll
        for (int kk = 0; kk < 32; kk += 8) {
            uint32_t af[2][4];
            #pragma unroll
            for (int mt = 0; mt < 2; mt++) {
                int r = mbase + mt * 16 + g;
                af[mt][0] = sP[r * PST + c * 32 + kk + t];
                af[mt][1] = sP[(r + 8) * PST + c * 32 + kk + t];
                af[mt][2] = sP[r * PST + c * 32 + kk + t + 4];
                af[mt][3] = sP[(r + 8) * PST + c * 32 + kk + t + 4];
            }
            uint32_t bf[8][2];
            #pragma unroll
            for (int nt = 0; nt < 8; nt++) {
                int d = nbase2 + nt * 8 + g;
                bf[nt][0] = sV[(kk + t) * VST + d];
                bf[nt][1] = sV[(kk + t + 4) * VST + d];
            }
            #pragma unroll
            for (int mt = 0; mt < 2; mt++)
                #pragma unroll
                for (int nt = 0; nt < 8; nt++)
                    mma_tf32(acc2[mt][nt], af[mt], bf[nt]);
        }
        __syncthreads();
    }

    #pragma unroll
    for (int mt = 0; mt < 2; mt++) {
        #pragma unroll
        for (int nt = 0; nt < 8; nt++) {
            int col = nbase2 + nt * 8 + 2 * t;
            int rr0 = l0 + mbase + mt * 16 + g;
            int rr1 = rr0 + 8;
            float* dst0 = &CTX[(size_t)(b * SEQ + rr0) * DIM + h * DHD + col];
            float* dst1 = &CTX[(size_t)(b * SEQ + rr1) * DIM + h * DHD + col];
            *reinterpret_cast<float2*>(dst0) = make_float2(acc2[mt][nt][0], acc2[mt][nt][1]);
            *reinterpret_cast<float2*>(dst1) = make_float2(acc2[mt][nt][2], acc2[mt][nt][3]);
        }
    }
}

// ---------------- fused weight prep: all transposes + dist pad --------------
__global__ void wprep(const float* __restrict__ Wq, const float* __restrict__ Wk,
                      const float* __restrict__ Wv, const float* __restrict__ Wo,
                      const float* __restrict__ Wi, const float* __restrict__ Wo2,
                      const float* __restrict__ dist,
                      float* __restrict__ WqkvT, float* __restrict__ WoT,
                      float* __restrict__ WiT, float* __restrict__ Wo2T,
                      float* __restrict__ dPp) {
    int z = blockIdx.z;
    int i = blockIdx.x * 256 + threadIdx.x;
    if (z < 3) {                          // Wq/Wk/Wv -> contiguous slabs
        const float* S = (z == 0) ? Wq : (z == 1) ? Wk : Wv;
        float* D = WqkvT + (size_t)z * (LNUM * DIM * DIM);
        int l = i >> 18;
        int w = i & 262143;
        int k = w >> 9, n = w & 511;
        D[(size_t)l * 262144 + n * 512 + k] = tf32_rna(S[i]);
    } else if (z == 3) {
        int l = i >> 18;
        int w = i & 262143;
        int k = w >> 9, n = w & 511;
        WoT[(size_t)l * 262144 + n * 512 + k] = tf32_rna(Wo[i]);
    } else if (z == 4) {
        if (i < LNUM * DIM * FFI) {
            int l = i >> 16, w = i & 65535;
            int k = w >> 7, n = w & 127;
            WiT[(size_t)l * 65536 + n * 512 + k] = tf32_rna(Wi[i]);
        }
    } else if (z == 5) {
        if (i < LNUM * FFI * DIM) {
            int l = i >> 16, w = i & 65535;
            int k = w >> 9, n = w & 511;
            Wo2T[(size_t)l * 65536 + n * 128 + k] = tf32_rna(Wo2[i]);
        }
    } else {
        if (i < DPAD * DHD) {
            int pp = i >> 7;
            dPp[i] = (pp < 511) ? tf32_rna(dist[i]) : 0.0f;
        }
    }
}

// --------------------------- embedding + LN ---------------------------------
__device__ __forceinline__ void block_reduce2(float& a, float& b) {
    __shared__ float sa[8], sb[8];
    int lane = threadIdx.x & 31, w = threadIdx.x >> 5;
    #pragma unroll
    for (int o = 16; o; o >>= 1) {
        a += __shfl_xor_sync(0xffffffffu, a, o);
        b += __shfl_xor_sync(0xffffffffu, b, o);
    }
    if (lane == 0) { sa[w] = a; sb[w] = b; }
    __syncthreads();
    if (w == 0) {
        a = (lane < 8) ? sa[lane] : 0.0f;
        b = (lane < 8) ? sb[lane] : 0.0f;
        #pragma unroll
        for (int o = 4; o; o >>= 1) {
            a += __shfl_xor_sync(0xffffffffu, a, o);
            b += __shfl_xor_sync(0xffffffffu, b, o);
        }
        if (lane == 0) { sa[0] = a; sb[0] = b; }
    }
    __syncthreads();
    a = sa[0]; b = sb[0];
}

__global__ void embed_ln(const int* __restrict__ ids, const float* __restrict__ inW,
                         const float* __restrict__ inb, const float* __restrict__ tok,
                         const float* __restrict__ g,  const float* __restrict__ bb,
                         float* __restrict__ X) {
    int tt = blockIdx.x, tid = threadIdx.x;
    float f[NFEAT];
    #pragma unroll
    for (int i = 0; i < NFEAT; i++) f[i] = (float)ids[tt * NFEAT + i];
    int d0 = tid, d1 = tid + 256;
    float v0 = inb[d0] + tok[d0];
    float v1 = inb[d1] + tok[d1];
    #pragma unroll
    for (int i = 0; i < NFEAT; i++) {
        v0 += f[i] * inW[i * DIM + d0];
        v1 += f[i] * inW[i * DIM + d1];
    }
    float s = v0 + v1, q = v0 * v0 + v1 * v1;
    block_reduce2(s, q);
    float mu  = s * (1.0f / DIM);
    float var = q * (1.0f / DIM) - mu * mu;
    float r   = rsqrtf(var + 1e-12f);
    size_t base = (size_t)tt * DIM;
    X[base + d0] = (v0 - mu) * r * g[d0] + bb[d0];
    X[base + d1] = (v1 - mu) * r * g[d1] + bb[d1];
}

// warp-per-token pure LayerNorm
__global__ __launch_bounds__(256) void ln_w(
    const float* __restrict__ in,
    const float* __restrict__ g, const float* __restrict__ bb,
    float* __restrict__ out) {
    int wid = threadIdx.x >> 5, lane = threadIdx.x & 31;
    int tt = blockIdx.x * 8 + wid;
    size_t base = (size_t)tt * DIM;
    float4 v[4];
    float s = 0.0f, q = 0.0f;
    #pragma unroll
    for (int i = 0; i < 4; i++) {
        int col = i * 128 + lane * 4;
        v[i] = *reinterpret_cast<const float4*>(&in[base + col]);
        s += v[i].x + v[i].y + v[i].z + v[i].w;
        q += v[i].x * v[i].x + v[i].y * v[i].y + v[i].z * v[i].z + v[i].w * v[i].w;
    }
    #pragma unroll
    for (int o = 16; o; o >>= 1) {
        s += __shfl_xor_sync(0xffffffffu, s, o);
        q += __shfl_xor_sync(0xffffffffu, q, o);
    }
    float mu  = s * (1.0f / DIM);
    float var = q * (1.0f / DIM) - mu * mu;
    float r   = rsqrtf(var + 1e-12f);
    #pragma unroll
    for (int i = 0; i < 4; i++) {
        int col = i * 128 + lane * 4;
        float4 g4 = *reinterpret_cast<const float4*>(&g[col]);
        float4 b4 = *reinterpret_cast<const float4*>(&bb[col]);
        float4 o4;
        o4.x = (v[i].x - mu) * r * g4.x + b4.x;
        o4.y = (v[i].y - mu) * r * g4.y + b4.y;
        o4.z = (v[i].z - mu) * r * g4.z + b4.z;
        o4.w = (v[i].w - mu) * r * g4.w + b4.w;
        *reinterpret_cast<float4*>(&out[base + col]) = o4;
    }
}

// ------------------------------ host driver ----------------------------------
extern "C" void kernel_launch(void* const* d_in, const int* in_sizes, int n_in,
                              void* d_out, int out_size) {
    (void)in_sizes; (void)n_in; (void)out_size;
    const int*   ids  = (const int*)  d_in[0];
    const float* mask = (const float*)d_in[1];
    const float* inW  = (const float*)d_in[2];
    const float* inb  = (const float*)d_in[3];
    const float* tok  = (const float*)d_in[4];
    const float* elg  = (const float*)d_in[5];
    const float* elb  = (const float*)d_in[6];
    const float* dist = (const float*)d_in[7];
    const float* Wq   = (const float*)d_in[8];
    const float* bq   = (const float*)d_in[9];
    const float* Wk   = (const float*)d_in[10];
    const float* bk   = (const float*)d_in[11];
    const float* Wv   = (const float*)d_in[12];
    const float* bv   = (const float*)d_in[13];
    const float* Wo   = (const float*)d_in[14];
    const float* bo   = (const float*)d_in[15];
    const float* ln1g = (const float*)d_in[16];
    const float* ln1b = (const float*)d_in[17];
    const float* Wi   = (const float*)d_in[18];
    const float* bi   = (const float*)d_in[19];
    const float* Wo2  = (const float*)d_in[20];
    const float* bo2  = (const float*)d_in[21];
    const float* ln2g = (const float*)d_in[22];
    const float* ln2b = (const float*)d_in[23];
    float* out = (float*)d_out;

    float *X, *QKV, *CTX, *TMP, *Hb, *QDKD, *dP;
    float *WqkvT, *WoT, *WiT, *Wo2T;
    cudaGetSymbolAddress((void**)&X,     g_X);
    cudaGetSymbolAddress((void**)&QKV,   g_QKV);
    cudaGetSymbolAddress((void**)&CTX,   g_CTX);
    cudaGetSymbolAddress((void**)&TMP,   g_TMP);
    cudaGetSymbolAddress((void**)&Hb,    g_Hb);
    cudaGetSymbolAddress((void**)&QDKD,  g_QDKD);
    cudaGetSymbolAddress((void**)&dP,    g_dP);
    cudaGetSymbolAddress((void**)&WqkvT, g_WqkvT);
    cudaGetSymbolAddress((void**)&WoT,   g_WoT);
    cudaGetSymbolAddress((void**)&WiT,   g_WiT);
    cudaGetSymbolAddress((void**)&Wo2T,  g_Wo2T);

    const int GEMM_SMEM  = NSTAGE * STAGEF * 4;
    const int FUSED_SMEM = FUSED_SMEMF * 4;
    cudaFuncSetAttribute(gemm_pipe<0,0>, cudaFuncAttributeMaxDynamicSharedMemorySize, GEMM_SMEM);
    cudaFuncSetAttribute(gemm_pipe<0,1>, cudaFuncAttributeMaxDynamicSharedMemorySize, GEMM_SMEM);
    cudaFuncSetAttribute(gemm_pipe<1,0>, cudaFuncAttributeMaxDynamicSharedMemorySize, GEMM_SMEM);
    cudaFuncSetAttribute(gemm_qkv,       cudaFuncAttributeMaxDynamicSharedMemorySize, GEMM_SMEM);
    cudaFuncSetAttribute(gemm_qd,        cudaFuncAttributeMaxDynamicSharedMemorySize, GEMM_SMEM);
    cudaFuncSetAttribute(fused_attn,     cudaFuncAttributeMaxDynamicSharedMemorySize, FUSED_SMEM);

    wprep<<<dim3(4096, 1, 7), 256>>>(Wq, Wk, Wv, Wo, Wi, Wo2, dist,
                                     WqkvT, WoT, WiT, Wo2T, dP);
    embed_ln<<<TOK, 256>>>(ids, inW, inb, tok, elg, elb, X);

    dim3 gQKV(DIM / 128, TOK / 128, 3);            // 4 x 256 x 3
    dim3 gQD(QCOLS / 128, ROWSBH / 128, 2);        // 3 x 1024 x 2
    dim3 gG(DIM / 128, TOK / 128);
    dim3 gGi(FFI / 128, TOK / 128);
    dim3 gA(SEQ / 128, BATCH * NHEAD);

    for (int l = 0; l < LNUM; l++) {
        const float* wqkv = WqkvT + (size_t)l * DIM * DIM;   // +z*LNUM*D*D inside
        const float* wot  = WoT   + (size_t)l * DIM * DIM;
        const float* wit  = WiT   + (size_t)l * FFI * DIM;
        const float* wo2t = Wo2T  + (size_t)l * DIM * FFI;

        gemm_qkv<<<gQKV, 256, GEMM_SMEM>>>(X, wqkv, bq + l * DIM, bk + l * DIM,
                                           bv + l * DIM, QKV);
        gemm_qd<<<gQD, 256, GEMM_SMEM>>>(QKV, dP, QDKD);

        fused_attn<<<gA, 256, FUSED_SMEM>>>(QKV, QDKD, mask, CTX);

        gemm_pipe<0,1><<<gG, 256, GEMM_SMEM>>>(CTX, wot, bo + l * DIM, X, TMP, DIM, DIM);
        ln_w<<<TOK / 8, 256>>>(TMP, ln1g + l * DIM, ln1b + l * DIM, X);

        gemm_pipe<1,0><<<gGi, 256, GEMM_SMEM>>>(X, wit, bi + l * FFI, nullptr, Hb, DIM, FFI);
        gemm_pipe<0,1><<<gG, 256, GEMM_SMEM>>>(Hb, wo2t, bo2 + l * DIM, X, TMP, FFI, DIM);
        ln_w<<<TOK / 8, 256>>>(TMP, ln2g + l * DIM, ln2b + l * DIM,
                               (l == LNUM - 1) ? out : X);
    }
}

// round 15
// speedup vs baseline: 1.5942x; 1.0094x over previous
#include <cuda_runtime.h>
#include <cuda_bf16.h>
#include <math.h>
#include <stdint.h>

// ---------------------------------------------------------------------------
// ExpressionBert forward. tf32 mma.sync + cp.async pipelines.
// Round 15: base = round 14 (best). Single change: QD/KD stored in bf16
// (halves the dominant 402MB/layer DRAM stream of gemm_qd + gather reads).
// ---------------------------------------------------------------------------

#define LNUM   4
#define DIM    512
#define NHEAD  4
#define DHD    128
#define FFI    128
#define SEQ    256
#define BATCH  128
#define NFEAT  6
#define TOK    (BATCH*SEQ)          // 32768
#define ROWSBH (BATCH*NHEAD*SEQ)    // 131072
#define QCOLS  384
#define DPAD   608

#define SM_SCALE 0.08838834764831845f  // 1/sqrt(128)

// ------------------------- static device scratch ---------------------------
__device__ float g_X   [TOK*DIM];
__device__ float g_QKV [(size_t)3*TOK*DIM];          // Q | K | V contiguous
__device__ float g_CTX [TOK*DIM];
__device__ float g_TMP [TOK*DIM];
__device__ float g_Hb  [TOK*FFI];
__device__ __nv_bfloat16 g_QDKD[(size_t)2*ROWSBH*QCOLS];  // QD | KD (bf16)
__device__ float g_dP  [DPAD*DHD];

__device__ float g_WqkvT[(size_t)3*LNUM*DIM*DIM];    // WqT | WkT | WvT
__device__ float g_WoT  [LNUM*DIM*DIM];
__device__ float g_WiT  [LNUM*FFI*DIM];
__device__ float g_Wo2T [LNUM*DIM*FFI];

// ------------------------------ helpers -------------------------------------
__device__ __forceinline__ uint32_t smem_u32(const void* p) {
    uint32_t a;
    asm("{ .reg .u64 t; cvta.to.shared.u64 t, %1; cvt.u32.u64 %0, t; }"
        : "=r"(a) : "l"(p));
    return a;
}

__device__ __forceinline__ float gelu_exact(float x) {
    return 0.5f * x * (1.0f + erff(x * 0.70710678118654752440f));
}

__device__ __forceinline__ float tf32_rna(float f) {
    uint32_t u;
    asm("cvt.rna.tf32.f32 %0, %1;" : "=r"(u) : "f"(f));
    return __uint_as_float(u);
}

__device__ __forceinline__ void mma_tf32(float* d, const uint32_t* a,
                                         const uint32_t* b) {
    asm volatile(
        "mma.sync.aligned.m16n8k8.row.col.f32.tf32.tf32.f32 "
        "{%0,%1,%2,%3}, {%4,%5,%6,%7}, {%8,%9}, {%0,%1,%2,%3};"
        : "+f"(d[0]), "+f"(d[1]), "+f"(d[2]), "+f"(d[3])
        : "r"(a[0]), "r"(a[1]), "r"(a[2]), "r"(a[3]), "r"(b[0]), "r"(b[1]));
}

__device__ __forceinline__ void cp16(uint32_t saddr, const void* gptr) {
    asm volatile("cp.async.cg.shared.global [%0], [%1], 16;"
                 :: "r"(saddr), "l"(gptr) : "memory");
}
#define CP_COMMIT() asm volatile("cp.async.commit_group;" ::: "memory")
#define CP_WAIT1()  asm volatile("cp.async.wait_group 1;" ::: "memory")

#define SST 36
#define STAGEF 9216
#define NSTAGE 3

#define FRAG_COMPUTE(sA, sB)                                                   \
    _Pragma("unroll")                                                          \
    for (int kk = 0; kk < 32; kk += 8) {                                       \
        uint32_t af[2][4];                                                     \
        _Pragma("unroll")                                                      \
        for (int mt = 0; mt < 2; mt++) {                                       \
            int r = mbase + mt * 16 + g;                                       \
            af[mt][0] = (sA)[r * SST + kk + t];                                \
            af[mt][1] = (sA)[(r + 8) * SST + kk + t];                          \
            af[mt][2] = (sA)[r * SST + kk + t + 4];                            \
            af[mt][3] = (sA)[(r + 8) * SST + kk + t + 4];                      \
        }                                                                      \
        uint32_t bf[8][2];                                                     \
        _Pragma("unroll")                                                      \
        for (int nt = 0; nt < 8; nt++) {                                       \
            int r = nbase + nt * 8 + g;                                        \
            bf[nt][0] = (sB)[r * SST + kk + t];                                \
            bf[nt][1] = (sB)[r * SST + kk + t + 4];                            \
        }                                                                      \
        _Pragma("unroll")                                                      \
        for (int mt = 0; mt < 2; mt++)                                         \
            _Pragma("unroll")                                                  \
            for (int nt = 0; nt < 8; nt++)                                     \
                mma_tf32(acc[mt][nt], af[mt], bf[nt]);                         \
    }

// main-loop body shared by all GEMM kernels (3-stage ring, 1 sync/chunk)
#define GEMM_MAINLOOP(Aptr, Bptr, Kdim)                                        \
    int nch = (Kdim) >> 5;                                                     \
    _Pragma("unroll")                                                          \
    for (int s = 0; s < 2; s++) {                                              \
        float* sA = dsm + s * STAGEF;                                          \
        float* sB = sA + 4608;                                                 \
        _Pragma("unroll")                                                      \
        for (int i = 0; i < 4; i++) {                                          \
            int idx = tid + i * 256, row = idx >> 3, seg = idx & 7;            \
            cp16(smem_u32(sA + row * SST + seg * 4),                           \
                 &(Aptr)[(size_t)(m0 + row) * (Kdim) + s * 32 + seg * 4]);     \
            cp16(smem_u32(sB + row * SST + seg * 4),                           \
                 &(Bptr)[(size_t)(n0 + row) * (Kdim) + s * 32 + seg * 4]);     \
        }                                                                      \
        CP_COMMIT();                                                           \
    }                                                                          \
    int stage = 0;                                                             \
    for (int c = 0; c < nch; c++) {                                            \
        CP_WAIT1();                                                            \
        __syncthreads();                                                       \
        if (c + 2 < nch) {                                                     \
            int s = (stage + 2) % NSTAGE;                                      \
            float* sA = dsm + s * STAGEF;                                      \
            float* sB = sA + 4608;                                             \
            _Pragma("unroll")                                                  \
            for (int i = 0; i < 4; i++) {                                      \
                int idx = tid + i * 256, row = idx >> 3, seg = idx & 7;        \
                cp16(smem_u32(sA + row * SST + seg * 4),                       \
                     &(Aptr)[(size_t)(m0 + row) * (Kdim) + (c + 2) * 32 + seg * 4]); \
                cp16(smem_u32(sB + row * SST + seg * 4),                       \
                     &(Bptr)[(size_t)(n0 + row) * (Kdim) + (c + 2) * 32 + seg * 4]); \
            }                                                                  \
        }                                                                      \
        CP_COMMIT();                                                           \
        const uint32_t* sA = (const uint32_t*)(dsm + stage * STAGEF);          \
        const uint32_t* sB = sA + 4608;                                        \
        FRAG_COMPUTE(sA, sB);                                                  \
        stage = (stage + 1) % NSTAGE;                                          \
    }

// ---------------- plain pipelined tf32 GEMM (Wo / FFN paths) ----------------
template<int GELU, int RESID>
__global__ __launch_bounds__(256, 2) void gemm_pipe(
    const float* __restrict__ A, const float* __restrict__ BT,
    const float* __restrict__ bias, const float* __restrict__ R,
    float* __restrict__ C, int K, int N) {
    extern __shared__ float dsm[];
    int tid  = threadIdx.x;
    int wid  = tid >> 5, lane = tid & 31;
    int g    = lane >> 2, t = lane & 3;
    int m0   = blockIdx.y * 128;
    int n0   = blockIdx.x * 128;
    int wm   = wid >> 1, wn = wid & 1;
    int mbase = wm * 32, nbase = wn * 64;

    float acc[2][8][4];
    #pragma unroll
    for (int i = 0; i < 2; i++)
        #pragma unroll
        for (int j = 0; j < 8; j++)
            #pragma unroll
            for (int q = 0; q < 4; q++) acc[i][j][q] = 0.0f;

    GEMM_MAINLOOP(A, BT, K)

    #pragma unroll
    for (int mt = 0; mt < 2; mt++) {
        #pragma unroll
        for (int nt = 0; nt < 8; nt++) {
            int col = n0 + nbase + nt * 8 + 2 * t;
            float b0 = bias ? bias[col]     : 0.0f;
            float b1 = bias ? bias[col + 1] : 0.0f;
            int r0 = m0 + mbase + mt * 16 + g;
            int r1 = r0 + 8;
            float v00 = acc[mt][nt][0] + b0, v01 = acc[mt][nt][1] + b1;
            float v10 = acc[mt][nt][2] + b0, v11 = acc[mt][nt][3] + b1;
            if (GELU) {
                v00 = gelu_exact(v00); v01 = gelu_exact(v01);
                v10 = gelu_exact(v10); v11 = gelu_exact(v11);
            }
            if (RESID) {
                float2 x0 = *reinterpret_cast<const float2*>(&R[(size_t)r0 * N + col]);
                float2 x1 = *reinterpret_cast<const float2*>(&R[(size_t)r1 * N + col]);
                v00 += x0.x; v01 += x0.y;
                v10 += x1.x; v11 += x1.y;
            }
            *reinterpret_cast<float2*>(&C[(size_t)r0 * N + col]) = make_float2(v00, v01);
            *reinterpret_cast<float2*>(&C[(size_t)r1 * N + col]) = make_float2(v10, v11);
        }
    }
}

// ---------------- batched QKV GEMM: z selects weight slab / bias / output ----
__global__ __launch_bounds__(256, 2) void gemm_qkv(
    const float* __restrict__ X, const float* __restrict__ Wbase,
    const float* __restrict__ b0p, const float* __restrict__ b1p,
    const float* __restrict__ b2p, float* __restrict__ QKV) {
    extern __shared__ float dsm[];
    int tid  = threadIdx.x;
    int wid  = tid >> 5, lane = tid & 31;
    int g    = lane >> 2, t = lane & 3;
    int m0   = blockIdx.y * 128;
    int n0   = blockIdx.x * 128;
    int z    = blockIdx.z;
    int wm   = wid >> 1, wn = wid & 1;
    int mbase = wm * 32, nbase = wn * 64;

    const float* BT   = Wbase + (size_t)z * (LNUM * DIM * DIM);
    const float* bias = (z == 0) ? b0p : (z == 1) ? b1p : b2p;
    float*       C    = QKV + (size_t)z * (TOK * DIM);

    float acc[2][8][4];
    #pragma unroll
    for (int i = 0; i < 2; i++)
        #pragma unroll
        for (int j = 0; j < 8; j++)
            #pragma unroll
            for (int q = 0; q < 4; q++) acc[i][j][q] = 0.0f;

    GEMM_MAINLOOP(X, BT, DIM)

    #pragma unroll
    for (int mt = 0; mt < 2; mt++) {
        #pragma unroll
        for (int nt = 0; nt < 8; nt++) {
            int col = n0 + nbase + nt * 8 + 2 * t;
            float b0 = bias[col], b1 = bias[col + 1];
            int r0 = m0 + mbase + mt * 16 + g;
            int r1 = r0 + 8;
            *reinterpret_cast<float2*>(&C[(size_t)r0 * DIM + col]) =
                make_float2(acc[mt][nt][0] + b0, acc[mt][nt][1] + b1);
            *reinterpret_cast<float2*>(&C[(size_t)r1 * DIM + col]) =
                make_float2(acc[mt][nt][2] + b0, acc[mt][nt][3] + b1);
        }
    }
}

// ---------------- batched QD/KD GEMM: bf16 output -----------------------------
__global__ __launch_bounds__(256, 2) void gemm_qd(
    const float* __restrict__ QKV, const float* __restrict__ dPp,
    __nv_bfloat16* __restrict__ QDKD) {
    extern __shared__ float dsm[];
    int tid  = threadIdx.x;
    int wid  = tid >> 5, lane = tid & 31;
    int g    = lane >> 2, t = lane & 3;
    int m0   = blockIdx.y * 128;
    int n0   = blockIdx.x * 128;
    int z    = blockIdx.z;
    int wm   = wid >> 1, wn = wid & 1;
    int mbase = wm * 32, nbase = wn * 64;

    const float* A = QKV + (size_t)z * (TOK * DIM);   // z=0 Q, z=1 K
    __nv_bfloat16* C = QDKD + (size_t)z * ((size_t)ROWSBH * QCOLS);
    int s0   = (m0 & 1023) >> 2;
    int woff = z ? (224 - s0) : s0;
    const float* BT = dPp + (size_t)woff * DHD;

    float acc[2][8][4];
    #pragma unroll
    for (int i = 0; i < 2; i++)
        #pragma unroll
        for (int j = 0; j < 8; j++)
            #pragma unroll
            for (int q = 0; q < 4; q++) acc[i][j][q] = 0.0f;

    GEMM_MAINLOOP(A, BT, DHD)

    #pragma unroll
    for (int mt = 0; mt < 2; mt++) {
        #pragma unroll
        for (int nt = 0; nt < 8; nt++) {
            int col = n0 + nbase + nt * 8 + 2 * t;
            int r0 = m0 + mbase + mt * 16 + g;
            int r1 = r0 + 8;
            __nv_bfloat162 p0, p1;
            p0.x = __float2bfloat16(acc[mt][nt][0]);
            p0.y = __float2bfloat16(acc[mt][nt][1]);
            p1.x = __float2bfloat16(acc[mt][nt][2]);
            p1.y = __float2bfloat16(acc[mt][nt][3]);
            *reinterpret_cast<__nv_bfloat162*>(&C[(size_t)r0 * QCOLS + col]) = p0;
            *reinterpret_cast<__nv_bfloat162*>(&C[(size_t)r1 * QCOLS + col]) = p1;
        }
    }
}

// ------------- fused attention: scores + softmax + ctx (r11, 256 thr) -------
#define PST 260
#define VST 132
#define OFF_Q0  0
#define OFF_Q1  4608
#define OFF_K0  9216
#define OFF_K1  18432
#define OFF_P   0
#define OFF_V0  33280
#define OFF_V1  37504
#define OFF_RED 41728
#define FUSED_SMEMF 42240

__global__ __launch_bounds__(256) void fused_attn(
    const float* __restrict__ QKV,
    const __nv_bfloat16* __restrict__ QDKD,
    const float* __restrict__ mask, float* __restrict__ CTX) {
    extern __shared__ float dsm[];
    int tid  = threadIdx.x;
    int wid  = tid >> 5, lane = tid & 31;
    int g    = lane >> 2, t = lane & 3;
    int l0   = blockIdx.x * 128;
    int bh   = blockIdx.y;
    int b    = bh >> 2, h = bh & 3;
    int wm   = wid >> 1, wn = wid & 1;
    int mbase = wm * 32;
    int nbase2 = wn * 64;

    const float* Qb = QKV + (size_t)b * SEQ * DIM + h * DHD;
    const float* Kb = Qb + (size_t)TOK * DIM;
    const float* Vb = Qb + (size_t)2 * TOK * DIM;
    const __nv_bfloat16* QD = QDKD;
    const __nv_bfloat16* KD = QDKD + (size_t)ROWSBH * QCOLS;

    float acc[2][16][4];
    #pragma unroll
    for (int i = 0; i < 2; i++)
        #pragma unroll
        for (int j = 0; j < 16; j++)
            #pragma unroll
            for (int q = 0; q < 4; q++) acc[i][j][q] = 0.0f;

    {
        float* sQ = dsm + OFF_Q0;
        float* sK = dsm + OFF_K0;
        #pragma unroll
        for (int i = 0; i < 4; i++) {
            int idx = tid + i * 256, row = idx >> 3, seg = idx & 7;
            cp16(smem_u32(sQ + row * SST + seg * 4),
                 &Qb[(size_t)(l0 + row) * DIM + seg * 4]);
        }
        #pragma unroll
        for (int i = 0; i < 8; i++) {
            int idx = tid + i * 256, row = idx >> 3, seg = idx & 7;
            cp16(smem_u32(sK + row * SST + seg * 4),
                 &Kb[(size_t)row * DIM + seg * 4]);
        }
        CP_COMMIT();
    }
    for (int c = 0; c < 4; c++) {
        if (c + 1 < 4) {
            float* sQ = dsm + ((c + 1) & 1 ? OFF_Q1 : OFF_Q0);
            float* sK = dsm + ((c + 1) & 1 ? OFF_K1 : OFF_K0);
            #pragma unroll
            for (int i = 0; i < 4; i++) {
                int idx = tid + i * 256, row = idx >> 3, seg = idx & 7;
                cp16(smem_u32(sQ + row * SST + seg * 4),
                     &Qb[(size_t)(l0 + row) * DIM + (c + 1) * 32 + seg * 4]);
            }
            #pragma unroll
            for (int i = 0; i < 8; i++) {
                int idx = tid + i * 256, row = idx >> 3, seg = idx & 7;
                cp16(smem_u32(sK + row * SST + seg * 4),
                     &Kb[(size_t)row * DIM + (c + 1) * 32 + seg * 4]);
            }
            CP_COMMIT();
        } else {
            CP_COMMIT();
        }
        CP_WAIT1();
        __syncthreads();
        const uint32_t* sQ = (const uint32_t*)(dsm + ((c & 1) ? OFF_Q1 : OFF_Q0));
        const uint32_t* sK = (const uint32_t*)(dsm + ((c & 1) ? OFF_K1 : OFF_K0));
        #pragma unroll
        for (int kk = 0; kk < 32; kk += 8) {
            uint32_t af[2][4];
            #pragma unroll
            for (int mt = 0; mt < 2; mt++) {
                int r = mbase + mt * 16 + g;
                af[mt][0] = sQ[r * SST + kk + t];
                af[mt][1] = sQ[(r + 8) * SST + kk + t];
                af[mt][2] = sQ[r * SST + kk + t + 4];
                af[mt][3] = sQ[(r + 8) * SST + kk + t + 4];
            }
            #pragma unroll
            for (int nth = 0; nth < 2; nth++) {
                uint32_t bf[8][2];
                #pragma unroll
                for (int j = 0; j < 8; j++) {
                    int r = wn * 128 + nth * 64 + j * 8 + g;
                    bf[j][0] = sK[r * SST + kk + t];
                    bf[j][1] = sK[r * SST + kk + t + 4];
                }
                #pragma unroll
                for (int mt = 0; mt < 2; mt++)
                    #pragma unroll
                    for (int j = 0; j < 8; j++)
                        mma_tf32(acc[mt][nth * 8 + j], af[mt], bf[j]);
            }
        }
        __syncthreads();
    }

    #pragma unroll
    for (int mt = 0; mt < 2; mt++) {
        int ll0 = l0 + mbase + mt * 16 + g;
        int ll1 = ll0 + 8;
        size_t qdr0 = ((size_t)(b * SEQ + ll0) * NHEAD + h) * QCOLS;
        size_t qdr1 = ((size_t)(b * SEQ + ll1) * NHEAD + h) * QCOLS;
        #pragma unroll
        for (int nt = 0; nt < 16; nt++) {
            int rr0 = wn * 128 + nt * 8 + 2 * t;
            int rr1 = rr0 + 1;
            size_t kdr0 = ((size_t)(b * SEQ + rr0) * NHEAD + h) * QCOLS;
            size_t kdr1 = ((size_t)(b * SEQ + rr1) * NHEAD + h) * QCOLS;
            float bias0 = (1.0f - mask[b * SEQ + rr0]) * (-1e9f);
            float bias1 = (1.0f - mask[b * SEQ + rr1]) * (-1e9f);
            int jq00 = (ll0 & 31) + 255 - rr0, jq01 = jq00 - 1;
            int jq10 = (ll1 & 31) + 255 - rr0, jq11 = jq10 - 1;
            int jk00 = ll0 - (rr0 & 31) + 31,  jk01 = ll0 - (rr1 & 31) + 31;
            int jk10 = ll1 - (rr0 & 31) + 31,  jk11 = ll1 - (rr1 & 31) + 31;
            float qd00 = __bfloat162float(QD[qdr0 + jq00]);
            float qd01 = __bfloat162float(QD[qdr0 + jq01]);
            float qd10 = __bfloat162float(QD[qdr1 + jq10]);
            float qd11 = __bfloat162float(QD[qdr1 + jq11]);
            float kd00 = __bfloat162float(KD[kdr0 + jk00]);
            float kd01 = __bfloat162float(KD[kdr1 + jk01]);
            float kd10 = __bfloat162float(KD[kdr0 + jk10]);
            float kd11 = __bfloat162float(KD[kdr1 + jk11]);
            acc[mt][nt][0] = (acc[mt][nt][0] + qd00 + kd00) * SM_SCALE + bias0;
            acc[mt][nt][1] = (acc[mt][nt][1] + qd01 + kd01) * SM_SCALE + bias1;
            acc[mt][nt][2] = (acc[mt][nt][2] + qd10 + kd10) * SM_SCALE + bias0;
            acc[mt][nt][3] = (acc[mt][nt][3] + qd11 + kd11) * SM_SCALE + bias1;
        }
    }

    float* rmax = dsm + OFF_RED;
    float* rsum = dsm + OFF_RED + 256;
    float mx[2][2];
    #pragma unroll
    for (int mt = 0; mt < 2; mt++)
        #pragma unroll
        for (int hf = 0; hf < 2; hf++) {
            float m = -1e30f;
            #pragma unroll
            for (int nt = 0; nt < 16; nt++) {
                m = fmaxf(m, acc[mt][nt][hf * 2]);
                m = fmaxf(m, acc[mt][nt][hf * 2 + 1]);
            }
            m = fmaxf(m, __shfl_xor_sync(0xffffffffu, m, 1));
            m = fmaxf(m, __shfl_xor_sync(0xffffffffu, m, 2));
            mx[mt][hf] = m;
        }
    if (t == 0) {
        #pragma unroll
        for (int mt = 0; mt < 2; mt++)
            #pragma unroll
            for (int hf = 0; hf < 2; hf++) {
                int lrow = mbase + mt * 16 + hf * 8 + g;
                rmax[wn * 128 + lrow] = mx[mt][hf];
            }
    }
    __syncthreads();
    #pragma unroll
    for (int mt = 0; mt < 2; mt++)
        #pragma unroll
        for (int hf = 0; hf < 2; hf++) {
            int lrow = mbase + mt * 16 + hf * 8 + g;
            float m = fmaxf(rmax[lrow], rmax[128 + lrow]);
            float s = 0.0f;
            #pragma unroll
            for (int nt = 0; nt < 16; nt++) {
                float e0 = __expf(acc[mt][nt][hf * 2]     - m);
                float e1 = __expf(acc[mt][nt][hf * 2 + 1] - m);
                acc[mt][nt][hf * 2]     = e0;
                acc[mt][nt][hf * 2 + 1] = e1;
                s += e0 + e1;
            }
            s += __shfl_xor_sync(0xffffffffu, s, 1);
            s += __shfl_xor_sync(0xffffffffu, s, 2);
            if (t == 0) rsum[wn * 128 + lrow] = s;
        }
    __syncthreads();
    #pragma unroll
    for (int mt = 0; mt < 2; mt++)
        #pragma unroll
        for (int hf = 0; hf < 2; hf++) {
            int lrow = mbase + mt * 16 + hf * 8 + g;
            float inv = 1.0f / (rsum[lrow] + rsum[128 + lrow]);
            #pragma unroll
            for (int nt = 0; nt < 16; nt++) {
                acc[mt][nt][hf * 2]     *= inv;
                acc[mt][nt][hf * 2 + 1] *= inv;
            }
        }
    __syncthreads();

    float* P = dsm + OFF_P;
    #pragma unroll
    for (int mt = 0; mt < 2; mt++) {
        int lr0 = mbase + mt * 16 + g;
        int lr1 = lr0 + 8;
        #pragma unroll
        for (int nt = 0; nt < 16; nt++) {
            int col = wn * 128 + nt * 8 + 2 * t;
            *reinterpret_cast<float2*>(&P[lr0 * PST + col]) =
                make_float2(acc[mt][nt][0], acc[mt][nt][1]);
            *reinterpret_cast<float2*>(&P[lr1 * PST + col]) =
                make_float2(acc[mt][nt][2], acc[mt][nt][3]);
        }
    }
    __syncthreads();

    float acc2[2][8][4];
    #pragma unroll
    for (int i = 0; i < 2; i++)
        #pragma unroll
        for (int j = 0; j < 8; j++)
            #pragma unroll
            for (int q = 0; q < 4; q++) acc2[i][j][q] = 0.0f;

    {
        float* sV = dsm + OFF_V0;
        #pragma unroll
        for (int i = 0; i < 4; i++) {
            int idx = tid + i * 256, r = idx >> 5, dseg = idx & 31;
            cp16(smem_u32(sV + r * VST + dseg * 4),
                 &Vb[(size_t)r * DIM + dseg * 4]);
        }
        CP_COMMIT();
    }
    for (int c = 0; c < 8; c++) {
        if (c + 1 < 8) {
            float* sV = dsm + (((c + 1) & 1) ? OFF_V1 : OFF_V0);
            #pragma unroll
            for (int i = 0; i < 4; i++) {
                int idx = tid + i * 256, r = idx >> 5, dseg = idx & 31;
                cp16(smem_u32(sV + r * VST + dseg * 4),
                     &Vb[(size_t)((c + 1) * 32 + r) * DIM + dseg * 4]);
            }
            CP_COMMIT();
        } else {
            CP_COMMIT();
        }
        CP_WAIT1();
        __syncthreads();
        const uint32_t* sP = (const uint32_t*)P;
        const uint32_t* sV = (const uint32_t*)(dsm + ((c & 1) ? OFF_V1 : OFF_V0));
        #pragma unroll
        for (int kk = 0; kk < 32; kk += 8) {
            uint32_t af[2][4];
            #pragma unroll
            for (int mt = 0; mt < 2; mt++) {
                int r = mbase + mt * 16 + g;
                af[mt][0] = sP[r * PST + c * 32 + kk + t];
                af[mt][1] = sP[(r + 8) * PST + c * 32 + kk + t];
                af[mt][2] = sP[r * PST + c * 32 + kk + t + 4];
                af[mt][3] = sP[(r + 8) * PST + c * 32 + kk + t + 4];
            }
            uint32_t bf[8][2];
            #pragma unroll
            for (int nt = 0; nt < 8; nt++) {
                int d = nbase2 + nt * 8 + g;
                bf[nt][0] = sV[(kk + t) * VST + d];
                bf[nt][1] = sV[(kk + t + 4) * VST + d];
            }
            #pragma unroll
            for (int mt = 0; mt < 2; mt++)
                #pragma unroll
                for (int nt = 0; nt < 8; nt++)
                    mma_tf32(acc2[mt][nt], af[mt], bf[nt]);
        }
        __syncthreads();
    }

    #pragma unroll
    for (int mt = 0; mt < 2; mt++) {
        #pragma unroll
        for (int nt = 0; nt < 8; nt++) {
            int col = nbase2 + nt * 8 + 2 * t;
            int rr0 = l0 + mbase + mt * 16 + g;
            int rr1 = rr0 + 8;
            float* dst0 = &CTX[(size_t)(b * SEQ + rr0) * DIM + h * DHD + col];
            float* dst1 = &CTX[(size_t)(b * SEQ + rr1) * DIM + h * DHD + col];
            *reinterpret_cast<float2*>(dst0) = make_float2(acc2[mt][nt][0], acc2[mt][nt][1]);
            *reinterpret_cast<float2*>(dst1) = make_float2(acc2[mt][nt][2], acc2[mt][nt][3]);
        }
    }
}

// ---------------- fused weight prep: all transposes + dist pad --------------
__global__ void wprep(const float* __restrict__ Wq, const float* __restrict__ Wk,
                      const float* __restrict__ Wv, const float* __restrict__ Wo,
                      const float* __restrict__ Wi, const float* __restrict__ Wo2,
                      const float* __restrict__ dist,
                      float* __restrict__ WqkvT, float* __restrict__ WoT,
                      float* __restrict__ WiT, float* __restrict__ Wo2T,
                      float* __restrict__ dPp) {
    int z = blockIdx.z;
    int i = blockIdx.x * 256 + threadIdx.x;
    if (z < 3) {
        const float* S = (z == 0) ? Wq : (z == 1) ? Wk : Wv;
        float* D = WqkvT + (size_t)z * (LNUM * DIM * DIM);
        int l = i >> 18;
        int w = i & 262143;
        int k = w >> 9, n = w & 511;
        D[(size_t)l * 262144 + n * 512 + k] = tf32_rna(S[i]);
    } else if (z == 3) {
        int l = i >> 18;
        int w = i & 262143;
        int k = w >> 9, n = w & 511;
        WoT[(size_t)l * 262144 + n * 512 + k] = tf32_rna(Wo[i]);
    } else if (z == 4) {
        if (i < LNUM * DIM * FFI) {
            int l = i >> 16, w = i & 65535;
            int k = w >> 7, n = w & 127;
            WiT[(size_t)l * 65536 + n * 512 + k] = tf32_rna(Wi[i]);
        }
    } else if (z == 5) {
        if (i < LNUM * FFI * DIM) {
            int l = i >> 16, w = i & 65535;
            int k = w >> 9, n = w & 511;
            Wo2T[(size_t)l * 65536 + n * 128 + k] = tf32_rna(Wo2[i]);
        }
    } else {
        if (i < DPAD * DHD) {
            int pp = i >> 7;
            dPp[i] = (pp < 511) ? tf32_rna(dist[i]) : 0.0f;
        }
    }
}

// --------------------------- embedding + LN ---------------------------------
__device__ __forceinline__ void block_reduce2(float& a, float& b) {
    __shared__ float sa[8], sb[8];
    int lane = threadIdx.x & 31, w = threadIdx.x >> 5;
    #pragma unroll
    for (int o = 16; o; o >>= 1) {
        a += __shfl_xor_sync(0xffffffffu, a, o);
        b += __shfl_xor_sync(0xffffffffu, b, o);
    }
    if (lane == 0) { sa[w] = a; sb[w] = b; }
    __syncthreads();
    if (w == 0) {
        a = (lane < 8) ? sa[lane] : 0.0f;
        b = (lane < 8) ? sb[lane] : 0.0f;
        #pragma unroll
        for (int o = 4; o; o >>= 1) {
            a += __shfl_xor_sync(0xffffffffu, a, o);
            b += __shfl_xor_sync(0xffffffffu, b, o);
        }
        if (lane == 0) { sa[0] = a; sb[0] = b; }
    }
    __syncthreads();
    a = sa[0]; b = sb[0];
}

__global__ void embed_ln(const int* __restrict__ ids, const float* __restrict__ inW,
                         const float* __restrict__ inb, const float* __restrict__ tok,
                         const float* __restrict__ g,  const float* __restrict__ bb,
                         float* __restrict__ X) {
    int tt = blockIdx.x, tid = threadIdx.x;
    float f[NFEAT];
    #pragma unroll
    for (int i = 0; i < NFEAT; i++) f[i] = (float)ids[tt * NFEAT + i];
    int d0 = tid, d1 = tid + 256;
    float v0 = inb[d0] + tok[d0];
    float v1 = inb[d1] + tok[d1];
    #pragma unroll
    for (int i = 0; i < NFEAT; i++) {
        v0 += f[i] * inW[i * DIM + d0];
        v1 += f[i] * inW[i * DIM + d1];
    }
    float s = v0 + v1, q = v0 * v0 + v1 * v1;
    block_reduce2(s, q);
    float mu  = s * (1.0f / DIM);
    float var = q * (1.0f / DIM) - mu * mu;
    float r   = rsqrtf(var + 1e-12f);
    size_t base = (size_t)tt * DIM;
    X[base + d0] = (v0 - mu) * r * g[d0] + bb[d0];
    X[base + d1] = (v1 - mu) * r * g[d1] + bb[d1];
}

// warp-per-token pure LayerNorm
__global__ __launch_bounds__(256) void ln_w(
    const float* __restrict__ in,
    const float* __restrict__ g, const float* __restrict__ bb,
    float* __restrict__ out) {
    int wid = threadIdx.x >> 5, lane = threadIdx.x & 31;
    int tt = blockIdx.x * 8 + wid;
    size_t base = (size_t)tt * DIM;
    float4 v[4];
    float s = 0.0f, q = 0.0f;
    #pragma unroll
    for (int i = 0; i < 4; i++) {
        int col = i * 128 + lane * 4;
        v[i] = *reinterpret_cast<const float4*>(&in[base + col]);
        s += v[i].x + v[i].y + v[i].z + v[i].w;
        q += v[i].x * v[i].x + v[i].y * v[i].y + v[i].z * v[i].z + v[i].w * v[i].w;
    }
    #pragma unroll
    for (int o = 16; o; o >>= 1) {
        s += __shfl_xor_sync(0xffffffffu, s, o);
        q += __shfl_xor_sync(0xffffffffu, q, o);
    }
    float mu  = s * (1.0f / DIM);
    float var = q * (1.0f / DIM) - mu * mu;
    float r   = rsqrtf(var + 1e-12f);
    #pragma unroll
    for (int i = 0; i < 4; i++) {
        int col = i * 128 + lane * 4;
        float4 g4 = *reinterpret_cast<const float4*>(&g[col]);
        float4 b4 = *reinterpret_cast<const float4*>(&bb[col]);
        float4 o4;
        o4.x = (v[i].x - mu) * r * g4.x + b4.x;
        o4.y = (v[i].y - mu) * r * g4.y + b4.y;
        o4.z = (v[i].z - mu) * r * g4.z + b4.z;
        o4.w = (v[i].w - mu) * r * g4.w + b4.w;
        *reinterpret_cast<float4*>(&out[base + col]) = o4;
    }
}

// ------------------------------ host driver ----------------------------------
extern "C" void kernel_launch(void* const* d_in, const int* in_sizes, int n_in,
                              void* d_out, int out_size) {
    (void)in_sizes; (void)n_in; (void)out_size;
    const int*   ids  = (const int*)  d_in[0];
    const float* mask = (const float*)d_in[1];
    const float* inW  = (const float*)d_in[2];
    const float* inb  = (const float*)d_in[3];
    const float* tok  = (const float*)d_in[4];
    const float* elg  = (const float*)d_in[5];
    const float* elb  = (const float*)d_in[6];
    const float* dist = (const float*)d_in[7];
    const float* Wq   = (const float*)d_in[8];
    const float* bq   = (const float*)d_in[9];
    const float* Wk   = (const float*)d_in[10];
    const float* bk   = (const float*)d_in[11];
    const float* Wv   = (const float*)d_in[12];
    const float* bv   = (const float*)d_in[13];
    const float* Wo   = (const float*)d_in[14];
    const float* bo   = (const float*)d_in[15];
    const float* ln1g = (const float*)d_in[16];
    const float* ln1b = (const float*)d_in[17];
    const float* Wi   = (const float*)d_in[18];
    const float* bi   = (const float*)d_in[19];
    const float* Wo2  = (const float*)d_in[20];
    const float* bo2  = (const float*)d_in[21];
    const float* ln2g = (const float*)d_in[22];
    const float* ln2b = (const float*)d_in[23];
    float* out = (float*)d_out;

    float *X, *QKV, *CTX, *TMP, *Hb, *dP;
    __nv_bfloat16* QDKD;
    float *WqkvT, *WoT, *WiT, *Wo2T;
    cudaGetSymbolAddress((void**)&X,     g_X);
    cudaGetSymbolAddress((void**)&QKV,   g_QKV);
    cudaGetSymbolAddress((void**)&CTX,   g_CTX);
    cudaGetSymbolAddress((void**)&TMP,   g_TMP);
    cudaGetSymbolAddress((void**)&Hb,    g_Hb);
    cudaGetSymbolAddress((void**)&QDKD,  g_QDKD);
    cudaGetSymbolAddress((void**)&dP,    g_dP);
    cudaGetSymbolAddress((void**)&WqkvT, g_WqkvT);
    cudaGetSymbolAddress((void**)&WoT,   g_WoT);
    cudaGetSymbolAddress((void**)&WiT,   g_WiT);
    cudaGetSymbolAddress((void**)&Wo2T,  g_Wo2T);

    const int GEMM_SMEM  = NSTAGE * STAGEF * 4;
    const int FUSED_SMEM = FUSED_SMEMF * 4;
    cudaFuncSetAttribute(gemm_pipe<0,0>, cudaFuncAttributeMaxDynamicSharedMemorySize, GEMM_SMEM);
    cudaFuncSetAttribute(gemm_pipe<0,1>, cudaFuncAttributeMaxDynamicSharedMemorySize, GEMM_SMEM);
    cudaFuncSetAttribute(gemm_pipe<1,0>, cudaFuncAttributeMaxDynamicSharedMemorySize, GEMM_SMEM);
    cudaFuncSetAttribute(gemm_qkv,       cudaFuncAttributeMaxDynamicSharedMemorySize, GEMM_SMEM);
    cudaFuncSetAttribute(gemm_qd,        cudaFuncAttributeMaxDynamicSharedMemorySize, GEMM_SMEM);
    cudaFuncSetAttribute(fused_attn,     cudaFuncAttributeMaxDynamicSharedMemorySize, FUSED_SMEM);

    wprep<<<dim3(4096, 1, 7), 256>>>(Wq, Wk, Wv, Wo, Wi, Wo2, dist,
                                     WqkvT, WoT, WiT, Wo2T, dP);
    embed_ln<<<TOK, 256>>>(ids, inW, inb, tok, elg, elb, X);

    dim3 gQKV(DIM / 128, TOK / 128, 3);
    dim3 gQD(QCOLS / 128, ROWSBH / 128, 2);
    dim3 gG(DIM / 128, TOK / 128);
    dim3 gGi(FFI / 128, TOK / 128);
    dim3 gA(SEQ / 128, BATCH * NHEAD);

    for (int l = 0; l < LNUM; l++) {
        const float* wqkv = WqkvT + (size_t)l * DIM * DIM;
        const float* wot  = WoT   + (size_t)l * DIM * DIM;
        const float* wit  = WiT   + (size_t)l * FFI * DIM;
        const float* wo2t = Wo2T  + (size_t)l * DIM * FFI;

        gemm_qkv<<<gQKV, 256, GEMM_SMEM>>>(X, wqkv, bq + l * DIM, bk + l * DIM,
                                           bv + l * DIM, QKV);
        gemm_qd<<<gQD, 256, GEMM_SMEM>>>(QKV, dP, QDKD);

        fused_attn<<<gA, 256, FUSED_SMEM>>>(QKV, QDKD, mask, CTX);

        gemm_pipe<0,1><<<gG, 256, GEMM_SMEM>>>(CTX, wot, bo + l * DIM, X, TMP, DIM, DIM);
        ln_w<<<TOK / 8, 256>>>(TMP, ln1g + l * DIM, ln1b + l * DIM, X);

        gemm_pipe<1,0><<<gGi, 256, GEMM_SMEM>>>(X, wit, bi + l * FFI, nullptr, Hb, DIM, FFI);
        gemm_pipe<0,1><<<gG, 256, GEMM_SMEM>>>(Hb, wo2t, bo2 + l * DIM, X, TMP, FFI, DIM);
        ln_w<<<TOK / 8, 256>>>(TMP, ln2g + l * DIM, ln2b + l * DIM,
                               (l == LNUM - 1) ? out : X);
    }
}

// round 16
// speedup vs baseline: 2.0732x; 1.3004x over previous
#include <cuda_runtime.h>
#include <cuda_fp16.h>
#include <math.h>
#include <stdint.h>

// ---------------------------------------------------------------------------
// ExpressionBert forward. Round 16: dense GEMMs on fp16 mma.sync m16n8k16
// (2x tf32 rate, same 10 mantissa bits; rn-rounded operands). Fragment path
// lifted from the round-4 verified kernel; 3-stage cp.async ring from r11.
// fused_attn stays tf32/fp32 (QD/KD + CTX now fp16).
// ---------------------------------------------------------------------------

#define LNUM   4
#define DIM    512
#define NHEAD  4
#define DHD    128
#define FFI    128
#define SEQ    256
#define BATCH  128
#define NFEAT  6
#define TOK    (BATCH*SEQ)          // 32768
#define ROWSBH (BATCH*NHEAD*SEQ)    // 131072
#define QCOLS  384
#define DPAD   608

#define SM_SCALE 0.08838834764831845f  // 1/sqrt(128)

// ------------------------- static device scratch ---------------------------
__device__ float  g_X   [TOK*DIM];                    // fp32 master (LN/resid)
__device__ __half g_Xh  [TOK*DIM];                    // fp16 GEMM operand
__device__ float  g_QKV [(size_t)3*TOK*DIM];          // fp32 for fused_attn
__device__ __half g_QKh [(size_t)2*TOK*DIM];          // fp16 Q|K for gemm_qd
__device__ __half g_CTXh[TOK*DIM];
__device__ float  g_TMP [TOK*DIM];
__device__ __half g_Hbh [TOK*FFI];
__device__ __half g_QDKD[(size_t)2*ROWSBH*QCOLS];     // fp16 QD | KD
__device__ __half g_dPh [DPAD*DHD];

__device__ __half g_WqkvTh[(size_t)3*LNUM*DIM*DIM];
__device__ __half g_WoTh  [LNUM*DIM*DIM];
__device__ __half g_WiTh  [LNUM*FFI*DIM];
__device__ __half g_Wo2Th [LNUM*DIM*FFI];

// ------------------------------ helpers -------------------------------------
__device__ __forceinline__ uint32_t smem_u32(const void* p) {
    uint32_t a;
    asm("{ .reg .u64 t; cvta.to.shared.u64 t, %1; cvt.u32.u64 %0, t; }"
        : "=r"(a) : "l"(p));
    return a;
}

__device__ __forceinline__ float gelu_exact(float x) {
    return 0.5f * x * (1.0f + erff(x * 0.70710678118654752440f));
}

__device__ __forceinline__ void mma_tf32(float* d, const uint32_t* a,
                                         const uint32_t* b) {
    asm volatile(
        "mma.sync.aligned.m16n8k8.row.col.f32.tf32.tf32.f32 "
        "{%0,%1,%2,%3}, {%4,%5,%6,%7}, {%8,%9}, {%0,%1,%2,%3};"
        : "+f"(d[0]), "+f"(d[1]), "+f"(d[2]), "+f"(d[3])
        : "r"(a[0]), "r"(a[1]), "r"(a[2]), "r"(a[3]), "r"(b[0]), "r"(b[1]));
}

__device__ __forceinline__ void mma_f16(float* d, const uint32_t* a,
                                        const uint32_t* b) {
    asm volatile(
        "mma.sync.aligned.m16n8k16.row.col.f32.f16.f16.f32 "
        "{%0,%1,%2,%3}, {%4,%5,%6,%7}, {%8,%9}, {%0,%1,%2,%3};"
        : "+f"(d[0]), "+f"(d[1]), "+f"(d[2]), "+f"(d[3])
        : "r"(a[0]), "r"(a[1]), "r"(a[2]), "r"(a[3]), "r"(b[0]), "r"(b[1]));
}

__device__ __forceinline__ void ldsm_x4(uint32_t& r0, uint32_t& r1,
                                        uint32_t& r2, uint32_t& r3, uint32_t addr) {
    asm volatile("ldmatrix.sync.aligned.m8n8.x4.shared.b16 {%0,%1,%2,%3}, [%4];"
                 : "=r"(r0), "=r"(r1), "=r"(r2), "=r"(r3) : "r"(addr));
}

__device__ __forceinline__ void cp16(uint32_t saddr, const void* gptr) {
    asm volatile("cp.async.cg.shared.global [%0], [%1], 16;"
                 :: "r"(saddr), "l"(gptr) : "memory");
}
#define CP_COMMIT() asm volatile("cp.async.commit_group;" ::: "memory")
#define CP_WAIT1()  asm volatile("cp.async.wait_group 1;" ::: "memory")

// -------------------- fp16 GEMM constants (round-4 layout) ------------------
#define SSTH 40            // halves per smem row (80B; banks (20r)%32 distinct)
#define STGH 10240         // halves per stage (A 128*40 + B 128*40)
#define NSTAGE 3
#define GEMM_SMEM_H (NSTAGE * STGH * 2)   // 61440 bytes

// fp16 3-stage mainloop. Needs in scope: tid, m0, n0, mbase, nbase, lane,
// acc[2][8][4], dsmh (half*), dsm0 (u32 base).
#define GEMM_MAINLOOP_H(Aptr, Bptr, Kdim)                                      \
    int nch = (Kdim) >> 5;                                                     \
    int m_idx  = lane >> 3;                                                    \
    int fr_row = ((m_idx & 1) << 3) + (lane & 7);                              \
    int fr_col = (m_idx >> 1) << 3;   /* halves */                             \
    uint32_t offA[2], offB[4];                                                 \
    _Pragma("unroll")                                                          \
    for (int mt = 0; mt < 2; mt++)                                             \
        offA[mt] = (uint32_t)(((mbase + mt * 16 + fr_row) * SSTH + fr_col) * 2);\
    _Pragma("unroll")                                                          \
    for (int np = 0; np < 4; np++)                                             \
        offB[np] = (uint32_t)(((nbase + np * 16 + fr_row) * SSTH + fr_col) * 2);\
    _Pragma("unroll")                                                          \
    for (int s = 0; s < 2; s++) {                                              \
        __half* sA = dsmh + s * STGH;                                          \
        __half* sB = sA + 5120;                                                \
        _Pragma("unroll")                                                      \
        for (int i = 0; i < 2; i++) {                                          \
            int idx = tid + i * 256, row = idx >> 2, seg = idx & 3;            \
            cp16(smem_u32(sA + row * SSTH + seg * 8),                          \
                 &(Aptr)[(size_t)(m0 + row) * (Kdim) + s * 32 + seg * 8]);     \
            cp16(smem_u32(sB + row * SSTH + seg * 8),                          \
                 &(Bptr)[(size_t)(n0 + row) * (Kdim) + s * 32 + seg * 8]);     \
        }                                                                      \
        CP_COMMIT();                                                           \
    }                                                                          \
    int stage = 0;                                                             \
    for (int c = 0; c < nch; c++) {                                            \
        CP_WAIT1();                                                            \
        __syncthreads();                                                       \
        if (c + 2 < nch) {                                                     \
            int s = (stage + 2) % NSTAGE;                                      \
            __half* sA = dsmh + s * STGH;                                      \
            __half* sB = sA + 5120;                                            \
            _Pragma("unroll")                                                  \
            for (int i = 0; i < 2; i++) {                                      \
                int idx = tid + i * 256, row = idx >> 2, seg = idx & 3;        \
                cp16(smem_u32(sA + row * SSTH + seg * 8),                      \
                     &(Aptr)[(size_t)(m0 + row) * (Kdim) + (c + 2) * 32 + seg * 8]); \
                cp16(smem_u32(sB + row * SSTH + seg * 8),                      \
                     &(Bptr)[(size_t)(n0 + row) * (Kdim) + (c + 2) * 32 + seg * 8]); \
            }                                                                  \
        }                                                                      \
        CP_COMMIT();                                                           \
        uint32_t aBase = dsm0 + (uint32_t)(stage * STGH * 2);                  \
        uint32_t bBase = aBase + 5120 * 2;                                     \
        _Pragma("unroll")                                                      \
        for (int kk = 0; kk < 32; kk += 16) {                                  \
            uint32_t af[2][4];                                                 \
            _Pragma("unroll")                                                  \
            for (int mt = 0; mt < 2; mt++)                                     \
                ldsm_x4(af[mt][0], af[mt][1], af[mt][2], af[mt][3],            \
                        aBase + offA[mt] + kk * 2);                            \
            uint32_t bf[8][2];                                                 \
            _Pragma("unroll")                                                  \
            for (int np = 0; np < 4; np++) {                                   \
                uint32_t r0, r1, r2, r3;                                       \
                ldsm_x4(r0, r1, r2, r3, bBase + offB[np] + kk * 2);            \
                bf[2 * np + 0][0] = r0; bf[2 * np + 0][1] = r2;                \
                bf[2 * np + 1][0] = r1; bf[2 * np + 1][1] = r3;                \
            }                                                                  \
            _Pragma("unroll")                                                  \
            for (int mt = 0; mt < 2; mt++)                                     \
                _Pragma("unroll")                                              \
                for (int nt = 0; nt < 8; nt++)                                 \
                    mma_f16(acc[mt][nt], af[mt], bf[nt]);                      \
        }                                                                      \
        stage = (stage + 1) % NSTAGE;                                          \
    }

#define ACC_INIT()                                                             \
    float acc[2][8][4];                                                        \
    _Pragma("unroll")                                                          \
    for (int i = 0; i < 2; i++)                                                \
        _Pragma("unroll")                                                      \
        for (int j = 0; j < 8; j++)                                            \
            _Pragma("unroll")                                                  \
            for (int q = 0; q < 4; q++) acc[i][j][q] = 0.0f;

// ---------------- generic fp16 GEMM (Wo / FFN paths) -------------------------
// OUTH: write half C; else fp32 C. RESID adds fp32 R.
template<int GELU, int RESID, int OUTH>
__global__ __launch_bounds__(256, 2) void gemm_h(
    const __half* __restrict__ A, const __half* __restrict__ BT,
    const float* __restrict__ bias, const float* __restrict__ R,
    float* __restrict__ C, __half* __restrict__ Ch, int K, int N) {
    extern __shared__ __half dsmh[];
    uint32_t dsm0 = smem_u32(dsmh);
    int tid  = threadIdx.x;
    int wid  = tid >> 5, lane = tid & 31;
    int g    = lane >> 2, t = lane & 3;
    int m0   = blockIdx.y * 128;
    int n0   = blockIdx.x * 128;
    int wm   = wid >> 1, wn = wid & 1;
    int mbase = wm * 32, nbase = wn * 64;

    ACC_INIT()
    GEMM_MAINLOOP_H(A, BT, K)

    #pragma unroll
    for (int mt = 0; mt < 2; mt++) {
        #pragma unroll
        for (int nt = 0; nt < 8; nt++) {
            int col = n0 + nbase + nt * 8 + 2 * t;
            float b0 = bias ? bias[col]     : 0.0f;
            float b1 = bias ? bias[col + 1] : 0.0f;
            int r0 = m0 + mbase + mt * 16 + g;
            int r1 = r0 + 8;
            float v00 = acc[mt][nt][0] + b0, v01 = acc[mt][nt][1] + b1;
            float v10 = acc[mt][nt][2] + b0, v11 = acc[mt][nt][3] + b1;
            if (GELU) {
                v00 = gelu_exact(v00); v01 = gelu_exact(v01);
                v10 = gelu_exact(v10); v11 = gelu_exact(v11);
            }
            if (RESID) {
                float2 x0 = *reinterpret_cast<const float2*>(&R[(size_t)r0 * N + col]);
                float2 x1 = *reinterpret_cast<const float2*>(&R[(size_t)r1 * N + col]);
                v00 += x0.x; v01 += x0.y;
                v10 += x1.x; v11 += x1.y;
            }
            if (OUTH) {
                *reinterpret_cast<__half2*>(&Ch[(size_t)r0 * N + col]) =
                    __floats2half2_rn(v00, v01);
                *reinterpret_cast<__half2*>(&Ch[(size_t)r1 * N + col]) =
                    __floats2half2_rn(v10, v11);
            } else {
                *reinterpret_cast<float2*>(&C[(size_t)r0 * N + col]) = make_float2(v00, v01);
                *reinterpret_cast<float2*>(&C[(size_t)r1 * N + col]) = make_float2(v10, v11);
            }
        }
    }
}

// ---------------- batched QKV GEMM (fp16 in, fp32 out + fp16 Q/K copies) -----
__global__ __launch_bounds__(256, 2) void gemm_qkv(
    const __half* __restrict__ Xh, const __half* __restrict__ Wbase,
    const float* __restrict__ b0p, const float* __restrict__ b1p,
    const float* __restrict__ b2p, float* __restrict__ QKV,
    __half* __restrict__ QKh) {
    extern __shared__ __half dsmh[];
    uint32_t dsm0 = smem_u32(dsmh);
    int tid  = threadIdx.x;
    int wid  = tid >> 5, lane = tid & 31;
    int g    = lane >> 2, t = lane & 3;
    int m0   = blockIdx.y * 128;
    int n0   = blockIdx.x * 128;
    int z    = blockIdx.z;
    int wm   = wid >> 1, wn = wid & 1;
    int mbase = wm * 32, nbase = wn * 64;

    const __half* BT   = Wbase + (size_t)z * (LNUM * DIM * DIM);
    const float*  bias = (z == 0) ? b0p : (z == 1) ? b1p : b2p;
    float*        C    = QKV + (size_t)z * (TOK * DIM);
    __half*       Ch   = (z < 2) ? (QKh + (size_t)z * (TOK * DIM)) : nullptr;

    ACC_INIT()
    GEMM_MAINLOOP_H(Xh, BT, DIM)

    #pragma unroll
    for (int mt = 0; mt < 2; mt++) {
        #pragma unroll
        for (int nt = 0; nt < 8; nt++) {
            int col = n0 + nbase + nt * 8 + 2 * t;
            float b0 = bias[col], b1 = bias[col + 1];
            int r0 = m0 + mbase + mt * 16 + g;
            int r1 = r0 + 8;
            float v00 = acc[mt][nt][0] + b0, v01 = acc[mt][nt][1] + b1;
            float v10 = acc[mt][nt][2] + b0, v11 = acc[mt][nt][3] + b1;
            *reinterpret_cast<float2*>(&C[(size_t)r0 * DIM + col]) = make_float2(v00, v01);
            *reinterpret_cast<float2*>(&C[(size_t)r1 * DIM + col]) = make_float2(v10, v11);
            if (Ch) {
                *reinterpret_cast<__half2*>(&Ch[(size_t)r0 * DIM + col]) =
                    __floats2half2_rn(v00, v01);
                *reinterpret_cast<__half2*>(&Ch[(size_t)r1 * DIM + col]) =
                    __floats2half2_rn(v10, v11);
            }
        }
    }
}

// ---------------- batched QD/KD GEMM (fp16 in/out) ---------------------------
__global__ __launch_bounds__(256, 2) void gemm_qd(
    const __half* __restrict__ QKh, const __half* __restrict__ dPh,
    __half* __restrict__ QDKD) {
    extern __shared__ __half dsmh[];
    uint32_t dsm0 = smem_u32(dsmh);
    int tid  = threadIdx.x;
    int wid  = tid >> 5, lane = tid & 31;
    int g    = lane >> 2, t = lane & 3;
    int m0   = blockIdx.y * 128;
    int n0   = blockIdx.x * 128;
    int z    = blockIdx.z;
    int wm   = wid >> 1, wn = wid & 1;
    int mbase = wm * 32, nbase = wn * 64;

    const __half* A = QKh + (size_t)z * (TOK * DIM);
    __half*       C = QDKD + (size_t)z * ((size_t)ROWSBH * QCOLS);
    int s0   = (m0 & 1023) >> 2;
    int woff = z ? (224 - s0) : s0;
    const __half* BT = dPh + (size_t)woff * DHD;

    ACC_INIT()
    GEMM_MAINLOOP_H(A, BT, DHD)

    #pragma unroll
    for (int mt = 0; mt < 2; mt++) {
        #pragma unroll
        for (int nt = 0; nt < 8; nt++) {
            int col = n0 + nbase + nt * 8 + 2 * t;
            int r0 = m0 + mbase + mt * 16 + g;
            int r1 = r0 + 8;
            *reinterpret_cast<__half2*>(&C[(size_t)r0 * QCOLS + col]) =
                __floats2half2_rn(acc[mt][nt][0], acc[mt][nt][1]);
            *reinterpret_cast<__half2*>(&C[(size_t)r1 * QCOLS + col]) =
                __floats2half2_rn(acc[mt][nt][2], acc[mt][nt][3]);
        }
    }
}

// ------------- fused attention (tf32, r11-verified; fp16 QDKD/CTX) ----------
#define SST 36
#define PST 260
#define VST 132
#define OFF_Q0  0
#define OFF_Q1  4608
#define OFF_K0  9216
#define OFF_K1  18432
#define OFF_P   0
#define OFF_V0  33280
#define OFF_V1  37504
#define OFF_RED 41728
#define FUSED_SMEMF 42240

__global__ __launch_bounds__(256) void fused_attn(
    const float* __restrict__ QKV,
    const __half* __restrict__ QDKD,
    const float* __restrict__ mask, __half* __restrict__ CTXh) {
    extern __shared__ float dsm[];
    int tid  = threadIdx.x;
    int wid  = tid >> 5, lane = tid & 31;
    int g    = lane >> 2, t = lane & 3;
    int l0   = blockIdx.x * 128;
    int bh   = blockIdx.y;
    int b    = bh >> 2, h = bh & 3;
    int wm   = wid >> 1, wn = wid & 1;
    int mbase = wm * 32;
    int nbase2 = wn * 64;

    const float* Qb = QKV + (size_t)b * SEQ * DIM + h * DHD;
    const float* Kb = Qb + (size_t)TOK * DIM;
    const float* Vb = Qb + (size_t)2 * TOK * DIM;
    const __half* QD = QDKD;
    const __half* KD = QDKD + (size_t)ROWSBH * QCOLS;

    float acc[2][16][4];
    #pragma unroll
    for (int i = 0; i < 2; i++)
        #pragma unroll
        for (int j = 0; j < 16; j++)
            #pragma unroll
            for (int q = 0; q < 4; q++) acc[i][j][q] = 0.0f;

    {
        float* sQ = dsm + OFF_Q0;
        float* sK = dsm + OFF_K0;
        #pragma unroll
        for (int i = 0; i < 4; i++) {
            int idx = tid + i * 256, row = idx >> 3, seg = idx & 7;
            cp16(smem_u32(sQ + row * SST + seg * 4),
                 &Qb[(size_t)(l0 + row) * DIM + seg * 4]);
        }
        #pragma unroll
        for (int i = 0; i < 8; i++) {
            int idx = tid + i * 256, row = idx >> 3, seg = idx & 7;
            cp16(smem_u32(sK + row * SST + seg * 4),
                 &Kb[(size_t)row * DIM + seg * 4]);
        }
        CP_COMMIT();
    }
    for (int c = 0; c < 4; c++) {
        if (c + 1 < 4) {
            float* sQ = dsm + ((c + 1) & 1 ? OFF_Q1 : OFF_Q0);
            float* sK = dsm + ((c + 1) & 1 ? OFF_K1 : OFF_K0);
            #pragma unroll
            for (int i = 0; i < 4; i++) {
                int idx = tid + i * 256, row = idx >> 3, seg = idx & 7;
                cp16(smem_u32(sQ + row * SST + seg * 4),
                     &Qb[(size_t)(l0 + row) * DIM + (c + 1) * 32 + seg * 4]);
            }
            #pragma unroll
            for (int i = 0; i < 8; i++) {
                int idx = tid + i * 256, row = idx >> 3, seg = idx & 7;
                cp16(smem_u32(sK + row * SST + seg * 4),
                     &Kb[(size_t)row * DIM + (c + 1) * 32 + seg * 4]);
            }
            CP_COMMIT();
        } else {
            CP_COMMIT();
        }
        CP_WAIT1();
        __syncthreads();
        const uint32_t* sQ = (const uint32_t*)(dsm + ((c & 1) ? OFF_Q1 : OFF_Q0));
        const uint32_t* sK = (const uint32_t*)(dsm + ((c & 1) ? OFF_K1 : OFF_K0));
        #pragma unroll
        for (int kk = 0; kk < 32; kk += 8) {
            uint32_t af[2][4];
            #pragma unroll
            for (int mt = 0; mt < 2; mt++) {
                int r = mbase + mt * 16 + g;
                af[mt][0] = sQ[r * SST + kk + t];
                af[mt][1] = sQ[(r + 8) * SST + kk + t];
                af[mt][2] = sQ[r * SST + kk + t + 4];
                af[mt][3] = sQ[(r + 8) * SST + kk + t + 4];
            }
            #pragma unroll
            for (int nth = 0; nth < 2; nth++) {
                uint32_t bf[8][2];
                #pragma unroll
                for (int j = 0; j < 8; j++) {
                    int r = wn * 128 + nth * 64 + j * 8 + g;
                    bf[j][0] = sK[r * SST + kk + t];
                    bf[j][1] = sK[r * SST + kk + t + 4];
                }
                #pragma unroll
                for (int mt = 0; mt < 2; mt++)
                    #pragma unroll
                    for (int j = 0; j < 8; j++)
                        mma_tf32(acc[mt][nth * 8 + j], af[mt], bf[j]);
            }
        }
        __syncthreads();
    }

    #pragma unroll
    for (int mt = 0; mt < 2; mt++) {
        int ll0 = l0 + mbase + mt * 16 + g;
        int ll1 = ll0 + 8;
        size_t qdr0 = ((size_t)(b * SEQ + ll0) * NHEAD + h) * QCOLS;
        size_t qdr1 = ((size_t)(b * SEQ + ll1) * NHEAD + h) * QCOLS;
        #pragma unroll
        for (int nt = 0; nt < 16; nt++) {
            int rr0 = wn * 128 + nt * 8 + 2 * t;
            int rr1 = rr0 + 1;
            size_t kdr0 = ((size_t)(b * SEQ + rr0) * NHEAD + h) * QCOLS;
            size_t kdr1 = ((size_t)(b * SEQ + rr1) * NHEAD + h) * QCOLS;
            float bias0 = (1.0f - mask[b * SEQ + rr0]) * (-1e9f);
            float bias1 = (1.0f - mask[b * SEQ + rr1]) * (-1e9f);
            int jq00 = (ll0 & 31) + 255 - rr0, jq01 = jq00 - 1;
            int jq10 = (ll1 & 31) + 255 - rr0, jq11 = jq10 - 1;
            int jk00 = ll0 - (rr0 & 31) + 31,  jk01 = ll0 - (rr1 & 31) + 31;
            int jk10 = ll1 - (rr0 & 31) + 31,  jk11 = ll1 - (rr1 & 31) + 31;
            float qd00 = __half2float(QD[qdr0 + jq00]);
            float qd01 = __half2float(QD[qdr0 + jq01]);
            float qd10 = __half2float(QD[qdr1 + jq10]);
            float qd11 = __half2float(QD[qdr1 + jq11]);
            float kd00 = __half2float(KD[kdr0 + jk00]);
            float kd01 = __half2float(KD[kdr1 + jk01]);
            float kd10 = __half2float(KD[kdr0 + jk10]);
            float kd11 = __half2float(KD[kdr1 + jk11]);
            acc[mt][nt][0] = (acc[mt][nt][0] + qd00 + kd00) * SM_SCALE + bias0;
            acc[mt][nt][1] = (acc[mt][nt][1] + qd01 + kd01) * SM_SCALE + bias1;
            acc[mt][nt][2] = (acc[mt][nt][2] + qd10 + kd10) * SM_SCALE + bias0;
            acc[mt][nt][3] = (acc[mt][nt][3] + qd11 + kd11) * SM_SCALE + bias1;
        }
    }

    float* rmax = dsm + OFF_RED;
    float* rsum = dsm + OFF_RED + 256;
    float mx[2][2];
    #pragma unroll
    for (int mt = 0; mt < 2; mt++)
        #pragma unroll
        for (int hf = 0; hf < 2; hf++) {
            float m = -1e30f;
            #pragma unroll
            for (int nt = 0; nt < 16; nt++) {
                m = fmaxf(m, acc[mt][nt][hf * 2]);
                m = fmaxf(m, acc[mt][nt][hf * 2 + 1]);
            }
            m = fmaxf(m, __shfl_xor_sync(0xffffffffu, m, 1));
            m = fmaxf(m, __shfl_xor_sync(0xffffffffu, m, 2));
            mx[mt][hf] = m;
        }
    if (t == 0) {
        #pragma unroll
        for (int mt = 0; mt < 2; mt++)
            #pragma unroll
            for (int hf = 0; hf < 2; hf++) {
                int lrow = mbase + mt * 16 + hf * 8 + g;
                rmax[wn * 128 + lrow] = mx[mt][hf];
            }
    }
    __syncthreads();
    #pragma unroll
    for (int mt = 0; mt < 2; mt++)
        #pragma unroll
        for (int hf = 0; hf < 2; hf++) {
            int lrow = mbase + mt * 16 + hf * 8 + g;
            float m = fmaxf(rmax[lrow], rmax[128 + lrow]);
            float s = 0.0f;
            #pragma unroll
            for (int nt = 0; nt < 16; nt++) {
                float e0 = __expf(acc[mt][nt][hf * 2]     - m);
                float e1 = __expf(acc[mt][nt][hf * 2 + 1] - m);
                acc[mt][nt][hf * 2]     = e0;
                acc[mt][nt][hf * 2 + 1] = e1;
                s += e0 + e1;
            }
            s += __shfl_xor_sync(0xffffffffu, s, 1);
            s += __shfl_xor_sync(0xffffffffu, s, 2);
            if (t == 0) rsum[wn * 128 + lrow] = s;
        }
    __syncthreads();
    #pragma unroll
    for (int mt = 0; mt < 2; mt++)
        #pragma unroll
        for (int hf = 0; hf < 2; hf++) {
            int lrow = mbase + mt * 16 + hf * 8 + g;
            float inv = 1.0f / (rsum[lrow] + rsum[128 + lrow]);
            #pragma unroll
            for (int nt = 0; nt < 16; nt++) {
                acc[mt][nt][hf * 2]     *= inv;
                acc[mt][nt][hf * 2 + 1] *= inv;
            }
        }
    __syncthreads();

    float* P = dsm + OFF_P;
    #pragma unroll
    for (int mt = 0; mt < 2; mt++) {
        int lr0 = mbase + mt * 16 + g;
        int lr1 = lr0 + 8;
        #pragma unroll
        for (int nt = 0; nt < 16; nt++) {
            int col = wn * 128 + nt * 8 + 2 * t;
            *reinterpret_cast<float2*>(&P[lr0 * PST + col]) =
                make_float2(acc[mt][nt][0], acc[mt][nt][1]);
            *reinterpret_cast<float2*>(&P[lr1 * PST + col]) =
                make_float2(acc[mt][nt][2], acc[mt][nt][3]);
        }
    }
    __syncthreads();

    float acc2[2][8][4];
    #pragma unroll
    for (int i = 0; i < 2; i++)
        #pragma unroll
        for (int j = 0; j < 8; j++)
            #pragma unroll
            for (int q = 0; q < 4; q++) acc2[i][j][q] = 0.0f;

    {
        float* sV = dsm + OFF_V0;
        #pragma unroll
        for (int i = 0; i < 4; i++) {
            int idx = tid + i * 256, r = idx >> 5, dseg = idx & 31;
            cp16(smem_u32(sV + r * VST + dseg * 4),
                 &Vb[(size_t)r * DIM + dseg * 4]);
        }
        CP_COMMIT();
    }
    for (int c = 0; c < 8; c++) {
        if (c + 1 < 8) {
            float* sV = dsm + (((c + 1) & 1) ? OFF_V1 : OFF_V0);
            #pragma unroll
            for (int i = 0; i < 4; i++) {
                int idx = tid + i * 256, r = idx >> 5, dseg = idx & 31;
                cp16(smem_u32(sV + r * VST + dseg * 4),
                     &Vb[(size_t)((c + 1) * 32 + r) * DIM + dseg * 4]);
            }
            CP_COMMIT();
        } else {
            CP_COMMIT();
        }
        CP_WAIT1();
        __syncthreads();
        const uint32_t* sP = (const uint32_t*)P;
        const uint32_t* sV = (const uint32_t*)(dsm + ((c & 1) ? OFF_V1 : OFF_V0));
        #pragma unroll
        for (int kk = 0; kk < 32; kk += 8) {
            uint32_t af[2][4];
            #pragma unroll
            for (int mt = 0; mt < 2; mt++) {
                int r = mbase + mt * 16 + g;
                af[mt][0] = sP[r * PST + c * 32 + kk + t];
                af[mt][1] = sP[(r + 8) * PST + c * 32 + kk + t];
                af[mt][2] = sP[r * PST + c * 32 + kk + t + 4];
                af[mt][3] = sP[(r + 8) * PST + c * 32 + kk + t + 4];
            }
            uint32_t bf[8][2];
            #pragma unroll
            for (int nt = 0; nt < 8; nt++) {
                int d = nbase2 + nt * 8 + g;
                bf[nt][0] = sV[(kk + t) * VST + d];
                bf[nt][1] = sV[(kk + t + 4) * VST + d];
            }
            #pragma unroll
            for (int mt = 0; mt < 2; mt++)
                #pragma unroll
                for (int nt = 0; nt < 8; nt++)
                    mma_tf32(acc2[mt][nt], af[mt], bf[nt]);
        }
        __syncthreads();
    }

    #pragma unroll
    for (int mt = 0; mt < 2; mt++) {
        #pragma unroll
        for (int nt = 0; nt < 8; nt++) {
            int col = nbase2 + nt * 8 + 2 * t;
            int rr0 = l0 + mbase + mt * 16 + g;
            int rr1 = rr0 + 8;
            *reinterpret_cast<__half2*>(&CTXh[(size_t)(b * SEQ + rr0) * DIM + h * DHD + col]) =
                __floats2half2_rn(acc2[mt][nt][0], acc2[mt][nt][1]);
            *reinterpret_cast<__half2*>(&CTXh[(size_t)(b * SEQ + rr1) * DIM + h * DHD + col]) =
                __floats2half2_rn(acc2[mt][nt][2], acc2[mt][nt][3]);
        }
    }
}

// ---------------- fused weight prep: transposes -> fp16 ---------------------
__global__ void wprep(const float* __restrict__ Wq, const float* __restrict__ Wk,
                      const float* __restrict__ Wv, const float* __restrict__ Wo,
                      const float* __restrict__ Wi, const float* __restrict__ Wo2,
                      const float* __restrict__ dist,
                      __half* __restrict__ WqkvTh, __half* __restrict__ WoTh,
                      __half* __restrict__ WiTh, __half* __restrict__ Wo2Th,
                      __half* __restrict__ dPh) {
    int z = blockIdx.z;
    int i = blockIdx.x * 256 + threadIdx.x;
    if (z < 3) {
        const float* S = (z == 0) ? Wq : (z == 1) ? Wk : Wv;
        __half* D = WqkvTh + (size_t)z * (LNUM * DIM * DIM);
        int l = i >> 18;
        int w = i & 262143;
        int k = w >> 9, n = w & 511;
        D[(size_t)l * 262144 + n * 512 + k] = __float2half_rn(S[i]);
    } else if (z == 3) {
        int l = i >> 18;
        int w = i & 262143;
        int k = w >> 9, n = w & 511;
        WoTh[(size_t)l * 262144 + n * 512 + k] = __float2half_rn(Wo[i]);
    } else if (z == 4) {
        if (i < LNUM * DIM * FFI) {
            int l = i >> 16, w = i & 65535;
            int k = w >> 7, n = w & 127;
            WiTh[(size_t)l * 65536 + n * 512 + k] = __float2half_rn(Wi[i]);
        }
    } else if (z == 5) {
        if (i < LNUM * FFI * DIM) {
            int l = i >> 16, w = i & 65535;
            int k = w >> 9, n = w & 511;
            Wo2Th[(size_t)l * 65536 + n * 128 + k] = __float2half_rn(Wo2[i]);
        }
    } else {
        if (i < DPAD * DHD) {
            int pp = i >> 7;
            dPh[i] = (pp < 511) ? __float2half_rn(dist[i]) : __float2half_rn(0.0f);
        }
    }
}

// --------------------------- embedding + LN ---------------------------------
__device__ __forceinline__ void block_reduce2(float& a, float& b) {
    __shared__ float sa[8], sb[8];
    int lane = threadIdx.x & 31, w = threadIdx.x >> 5;
    #pragma unroll
    for (int o = 16; o; o >>= 1) {
        a += __shfl_xor_sync(0xffffffffu, a, o);
        b += __shfl_xor_sync(0xffffffffu, b, o);
    }
    if (lane == 0) { sa[w] = a; sb[w] = b; }
    __syncthreads();
    if (w == 0) {
        a = (lane < 8) ? sa[lane] : 0.0f;
        b = (lane < 8) ? sb[lane] : 0.0f;
        #pragma unroll
        for (int o = 4; o; o >>= 1) {
            a += __shfl_xor_sync(0xffffffffu, a, o);
            b += __shfl_xor_sync(0xffffffffu, b, o);
        }
        if (lane == 0) { sa[0] = a; sb[0] = b; }
    }
    __syncthreads();
    a = sa[0]; b = sb[0];
}

__global__ void embed_ln(const int* __restrict__ ids, const float* __restrict__ inW,
                         const float* __restrict__ inb, const float* __restrict__ tok,
                         const float* __restrict__ g,  const float* __restrict__ bb,
                         float* __restrict__ X, __half* __restrict__ Xh) {
    int tt = blockIdx.x, tid = threadIdx.x;
    float f[NFEAT];
    #pragma unroll
    for (int i = 0; i < NFEAT; i++) f[i] = (float)ids[tt * NFEAT + i];
    int d0 = tid, d1 = tid + 256;
    float v0 = inb[d0] + tok[d0];
    float v1 = inb[d1] + tok[d1];
    #pragma unroll
    for (int i = 0; i < NFEAT; i++) {
        v0 += f[i] * inW[i * DIM + d0];
        v1 += f[i] * inW[i * DIM + d1];
    }
    float s = v0 + v1, q = v0 * v0 + v1 * v1;
    block_reduce2(s, q);
    float mu  = s * (1.0f / DIM);
    float var = q * (1.0f / DIM) - mu * mu;
    float r   = rsqrtf(var + 1e-12f);
    float o0 = (v0 - mu) * r * g[d0] + bb[d0];
    float o1 = (v1 - mu) * r * g[d1] + bb[d1];
    size_t base = (size_t)tt * DIM;
    X[base + d0] = o0;  X[base + d1] = o1;
    Xh[base + d0] = __float2half_rn(o0);
    Xh[base + d1] = __float2half_rn(o1);
}

// warp-per-token pure LayerNorm, dual fp32+fp16 output
__global__ __launch_bounds__(256) void ln_w(
    const float* __restrict__ in,
    const float* __restrict__ g, const float* __restrict__ bb,
    float* __restrict__ out, __half* __restrict__ outh) {
    int wid = threadIdx.x >> 5, lane = threadIdx.x & 31;
    int tt = blockIdx.x * 8 + wid;
    size_t base = (size_t)tt * DIM;
    float4 v[4];
    float s = 0.0f, q = 0.0f;
    #pragma unroll
    for (int i = 0; i < 4; i++) {
        int col = i * 128 + lane * 4;
        v[i] = *reinterpret_cast<const float4*>(&in[base + col]);
        s += v[i].x + v[i].y + v[i].z + v[i].w;
        q += v[i].x * v[i].x + v[i].y * v[i].y + v[i].z * v[i].z + v[i].w * v[i].w;
    }
    #pragma unroll
    for (int o = 16; o; o >>= 1) {
        s += __shfl_xor_sync(0xffffffffu, s, o);
        q += __shfl_xor_sync(0xffffffffu, q, o);
    }
    float mu  = s * (1.0f / DIM);
    float var = q * (1.0f / DIM) - mu * mu;
    float r   = rsqrtf(var + 1e-12f);
    #pragma unroll
    for (int i = 0; i < 4; i++) {
        int col = i * 128 + lane * 4;
        float4 g4 = *reinterpret_cast<const float4*>(&g[col]);
        float4 b4 = *reinterpret_cast<const float4*>(&bb[col]);
        float4 o4;
        o4.x = (v[i].x - mu) * r * g4.x + b4.x;
        o4.y = (v[i].y - mu) * r * g4.y + b4.y;
        o4.z = (v[i].z - mu) * r * g4.z + b4.z;
        o4.w = (v[i].w - mu) * r * g4.w + b4.w;
        *reinterpret_cast<float4*>(&out[base + col]) = o4;
        __half2 h0 = __floats2half2_rn(o4.x, o4.y);
        __half2 h1 = __floats2half2_rn(o4.z, o4.w);
        *reinterpret_cast<__half2*>(&outh[base + col])     = h0;
        *reinterpret_cast<__half2*>(&outh[base + col + 2]) = h1;
    }
}

// ------------------------------ host driver ----------------------------------
extern "C" void kernel_launch(void* const* d_in, const int* in_sizes, int n_in,
                              void* d_out, int out_size) {
    (void)in_sizes; (void)n_in; (void)out_size;
    const int*   ids  = (const int*)  d_in[0];
    const float* mask = (const float*)d_in[1];
    const float* inW  = (const float*)d_in[2];
    const float* inb  = (const float*)d_in[3];
    const float* tok  = (const float*)d_in[4];
    const float* elg  = (const float*)d_in[5];
    const float* elb  = (const float*)d_in[6];
    const float* dist = (const float*)d_in[7];
    const float* Wq   = (const float*)d_in[8];
    const float* bq   = (const float*)d_in[9];
    const float* Wk   = (const float*)d_in[10];
    const float* bk   = (const float*)d_in[11];
    const float* Wv   = (const float*)d_in[12];
    const float* bv   = (const float*)d_in[13];
    const float* Wo   = (const float*)d_in[14];
    const float* bo   = (const float*)d_in[15];
    const float* ln1g = (const float*)d_in[16];
    const float* ln1b = (const float*)d_in[17];
    const float* Wi   = (const float*)d_in[18];
    const float* bi   = (const float*)d_in[19];
    const float* Wo2  = (const float*)d_in[20];
    const float* bo2  = (const float*)d_in[21];
    const float* ln2g = (const float*)d_in[22];
    const float* ln2b = (const float*)d_in[23];
    float* out = (float*)d_out;

    float *X, *QKV, *TMP;
    __half *Xh, *QKh, *CTXh, *Hbh, *QDKD, *dPh;
    __half *WqkvTh, *WoTh, *WiTh, *Wo2Th;
    cudaGetSymbolAddress((void**)&X,      g_X);
    cudaGetSymbolAddress((void**)&Xh,     g_Xh);
    cudaGetSymbolAddress((void**)&QKV,    g_QKV);
    cudaGetSymbolAddress((void**)&QKh,    g_QKh);
    cudaGetSymbolAddress((void**)&CTXh,   g_CTXh);
    cudaGetSymbolAddress((void**)&TMP,    g_TMP);
    cudaGetSymbolAddress((void**)&Hbh,    g_Hbh);
    cudaGetSymbolAddress((void**)&QDKD,   g_QDKD);
    cudaGetSymbolAddress((void**)&dPh,    g_dPh);
    cudaGetSymbolAddress((void**)&WqkvTh, g_WqkvTh);
    cudaGetSymbolAddress((void**)&WoTh,   g_WoTh);
    cudaGetSymbolAddress((void**)&WiTh,   g_WiTh);
    cudaGetSymbolAddress((void**)&Wo2Th,  g_Wo2Th);

    const int FUSED_SMEM = FUSED_SMEMF * 4;
    cudaFuncSetAttribute(gemm_h<0,1,0>, cudaFuncAttributeMaxDynamicSharedMemorySize, GEMM_SMEM_H);
    cudaFuncSetAttribute(gemm_h<1,0,1>, cudaFuncAttributeMaxDynamicSharedMemorySize, GEMM_SMEM_H);
    cudaFuncSetAttribute(gemm_qkv,      cudaFuncAttributeMaxDynamicSharedMemorySize, GEMM_SMEM_H);
    cudaFuncSetAttribute(gemm_qd,       cudaFuncAttributeMaxDynamicSharedMemorySize, GEMM_SMEM_H);
    cudaFuncSetAttribute(fused_attn,    cudaFuncAttributeMaxDynamicSharedMemorySize, FUSED_SMEM);

    wprep<<<dim3(4096, 1, 7), 256>>>(Wq, Wk, Wv, Wo, Wi, Wo2, dist,
                                     WqkvTh, WoTh, WiTh, Wo2Th, dPh);
    embed_ln<<<TOK, 256>>>(ids, inW, inb, tok, elg, elb, X, Xh);

    dim3 gQKV(DIM / 128, TOK / 128, 3);
    dim3 gQD(QCOLS / 128, ROWSBH / 128, 2);
    dim3 gG(DIM / 128, TOK / 128);
    dim3 gGi(FFI / 128, TOK / 128);
    dim3 gA(SEQ / 128, BATCH * NHEAD);

    for (int l = 0; l < LNUM; l++) {
        const __half* wqkv = WqkvTh + (size_t)l * DIM * DIM;   // +z slab inside
        const __half* wot  = WoTh   + (size_t)l * DIM * DIM;
        const __half* wit  = WiTh   + (size_t)l * FFI * DIM;
        const __half* wo2t = Wo2Th  + (size_t)l * DIM * FFI;

        gemm_qkv<<<gQKV, 256, GEMM_SMEM_H>>>(Xh, wqkv, bq + l * DIM, bk + l * DIM,
                                             bv + l * DIM, QKV, QKh);
        gemm_qd<<<gQD, 256, GEMM_SMEM_H>>>(QKh, dPh, QDKD);

        fused_attn<<<gA, 256, FUSED_SMEM>>>(QKV, QDKD, mask, CTXh);

        gemm_h<0,1,0><<<gG, 256, GEMM_SMEM_H>>>(CTXh, wot, bo + l * DIM, X,
                                                TMP, nullptr, DIM, DIM);
        ln_w<<<TOK / 8, 256>>>(TMP, ln1g + l * DIM, ln1b + l * DIM, X, Xh);

        gemm_h<1,0,1><<<gGi, 256, GEMM_SMEM_H>>>(Xh, wit, bi + l * FFI, nullptr,
                                                 nullptr, Hbh, DIM, FFI);
        gemm_h<0,1,0><<<gG, 256, GEMM_SMEM_H>>>(Hbh, wo2t, bo2 + l * DIM, X,
                                                TMP, nullptr, FFI, DIM);
        ln_w<<<TOK / 8, 256>>>(TMP, ln2g + l * DIM, ln2b + l * DIM,
                               (l == LNUM - 1) ? out : X, Xh);
    }
}

// round 17
// speedup vs baseline: 2.1748x; 1.0490x over previous
#include <cuda_runtime.h>
#include <cuda_fp16.h>
#include <math.h>
#include <stdint.h>

// ---------------------------------------------------------------------------
// ExpressionBert forward. Round 17: base = round 16 (best, fp16 dense GEMMs).
// Changes: (1) fused_attn phase-1 (Q.K^T) now fp16 mma m16n8k16 reading the
// existing fp16 Q/K buffer; (2) gemm_qkv drops dead fp32 Q/K writes (only V
// needs fp32). Phase-2 (P.V) stays tf32/fp32, epilogue/softmax unchanged.
// ---------------------------------------------------------------------------

#define LNUM   4
#define DIM    512
#define NHEAD  4
#define DHD    128
#define FFI    128
#define SEQ    256
#define BATCH  128
#define NFEAT  6
#define TOK    (BATCH*SEQ)          // 32768
#define ROWSBH (BATCH*NHEAD*SEQ)    // 131072
#define QCOLS  384
#define DPAD   608

#define SM_SCALE 0.08838834764831845f  // 1/sqrt(128)

// ------------------------- static device scratch ---------------------------
__device__ float  g_X   [TOK*DIM];
__device__ __half g_Xh  [TOK*DIM];
__device__ float  g_V32 [TOK*DIM];                    // fp32 V (fused phase 2)
__device__ __half g_QKh [(size_t)2*TOK*DIM];          // fp16 Q | K
__device__ __half g_CTXh[TOK*DIM];
__device__ float  g_TMP [TOK*DIM];
__device__ __half g_Hbh [TOK*FFI];
__device__ __half g_QDKD[(size_t)2*ROWSBH*QCOLS];
__device__ __half g_dPh [DPAD*DHD];

__device__ __half g_WqkvTh[(size_t)3*LNUM*DIM*DIM];
__device__ __half g_WoTh  [LNUM*DIM*DIM];
__device__ __half g_WiTh  [LNUM*FFI*DIM];
__device__ __half g_Wo2Th [LNUM*DIM*FFI];

// ------------------------------ helpers -------------------------------------
__device__ __forceinline__ uint32_t smem_u32(const void* p) {
    uint32_t a;
    asm("{ .reg .u64 t; cvta.to.shared.u64 t, %1; cvt.u32.u64 %0, t; }"
        : "=r"(a) : "l"(p));
    return a;
}

__device__ __forceinline__ float gelu_exact(float x) {
    return 0.5f * x * (1.0f + erff(x * 0.70710678118654752440f));
}

__device__ __forceinline__ void mma_tf32(float* d, const uint32_t* a,
                                         const uint32_t* b) {
    asm volatile(
        "mma.sync.aligned.m16n8k8.row.col.f32.tf32.tf32.f32 "
        "{%0,%1,%2,%3}, {%4,%5,%6,%7}, {%8,%9}, {%0,%1,%2,%3};"
        : "+f"(d[0]), "+f"(d[1]), "+f"(d[2]), "+f"(d[3])
        : "r"(a[0]), "r"(a[1]), "r"(a[2]), "r"(a[3]), "r"(b[0]), "r"(b[1]));
}

__device__ __forceinline__ void mma_f16(float* d, const uint32_t* a,
                                        const uint32_t* b) {
    asm volatile(
        "mma.sync.aligned.m16n8k16.row.col.f32.f16.f16.f32 "
        "{%0,%1,%2,%3}, {%4,%5,%6,%7}, {%8,%9}, {%0,%1,%2,%3};"
        : "+f"(d[0]), "+f"(d[1]), "+f"(d[2]), "+f"(d[3])
        : "r"(a[0]), "r"(a[1]), "r"(a[2]), "r"(a[3]), "r"(b[0]), "r"(b[1]));
}

__device__ __forceinline__ void ldsm_x4(uint32_t& r0, uint32_t& r1,
                                        uint32_t& r2, uint32_t& r3, uint32_t addr) {
    asm volatile("ldmatrix.sync.aligned.m8n8.x4.shared.b16 {%0,%1,%2,%3}, [%4];"
                 : "=r"(r0), "=r"(r1), "=r"(r2), "=r"(r3) : "r"(addr));
}

__device__ __forceinline__ void cp16(uint32_t saddr, const void* gptr) {
    asm volatile("cp.async.cg.shared.global [%0], [%1], 16;"
                 :: "r"(saddr), "l"(gptr) : "memory");
}
#define CP_COMMIT() asm volatile("cp.async.commit_group;" ::: "memory")
#define CP_WAIT1()  asm volatile("cp.async.wait_group 1;" ::: "memory")

// -------------------- fp16 GEMM constants (round-16 verified) ---------------
#define SSTH 40
#define STGH 10240
#define NSTAGE 3
#define GEMM_SMEM_H (NSTAGE * STGH * 2)   // 61440 bytes

#define GEMM_MAINLOOP_H(Aptr, Bptr, Kdim)                                      \
    int nch = (Kdim) >> 5;                                                     \
    int m_idx  = lane >> 3;                                                    \
    int fr_row = ((m_idx & 1) << 3) + (lane & 7);                              \
    int fr_col = (m_idx >> 1) << 3;                                            \
    uint32_t offA[2], offB[4];                                                 \
    _Pragma("unroll")                                                          \
    for (int mt = 0; mt < 2; mt++)                                             \
        offA[mt] = (uint32_t)(((mbase + mt * 16 + fr_row) * SSTH + fr_col) * 2);\
    _Pragma("unroll")                                                          \
    for (int np = 0; np < 4; np++)                                             \
        offB[np] = (uint32_t)(((nbase + np * 16 + fr_row) * SSTH + fr_col) * 2);\
    _Pragma("unroll")                                                          \
    for (int s = 0; s < 2; s++) {                                              \
        __half* sA = dsmh + s * STGH;                                          \
        __half* sB = sA + 5120;                                                \
        _Pragma("unroll")                                                      \
        for (int i = 0; i < 2; i++) {                                          \
            int idx = tid + i * 256, row = idx >> 2, seg = idx & 3;            \
            cp16(smem_u32(sA + row * SSTH + seg * 8),                          \
                 &(Aptr)[(size_t)(m0 + row) * (Kdim) + s * 32 + seg * 8]);     \
            cp16(smem_u32(sB + row * SSTH + seg * 8),                          \
                 &(Bptr)[(size_t)(n0 + row) * (Kdim) + s * 32 + seg * 8]);     \
        }                                                                      \
        CP_COMMIT();                                                           \
    }                                                                          \
    int stage = 0;                                                             \
    for (int c = 0; c < nch; c++) {                                            \
        CP_WAIT1();                                                            \
        __syncthreads();                                                       \
        if (c + 2 < nch) {                                                     \
            int s = (stage + 2) % NSTAGE;                                      \
            __half* sA = dsmh + s * STGH;                                      \
            __half* sB = sA + 5120;                                            \
            _Pragma("unroll")                                                  \
            for (int i = 0; i < 2; i++) {                                      \
                int idx = tid + i * 256, row = idx >> 2, seg = idx & 3;        \
                cp16(smem_u32(sA + row * SSTH + seg * 8),                      \
                     &(Aptr)[(size_t)(m0 + row) * (Kdim) + (c + 2) * 32 + seg * 8]); \
                cp16(smem_u32(sB + row * SSTH + seg * 8),                      \
                     &(Bptr)[(size_t)(n0 + row) * (Kdim) + (c + 2) * 32 + seg * 8]); \
            }                                                                  \
        }                                                                      \
        CP_COMMIT();                                                           \
        uint32_t aBase = dsm0 + (uint32_t)(stage * STGH * 2);                  \
        uint32_t bBase = aBase + 5120 * 2;                                     \
        _Pragma("unroll")                                                      \
        for (int kk = 0; kk < 32; kk += 16) {                                  \
            uint32_t af[2][4];                                                 \
            _Pragma("unroll")                                                  \
            for (int mt = 0; mt < 2; mt++)                                     \
                ldsm_x4(af[mt][0], af[mt][1], af[mt][2], af[mt][3],            \
                        aBase + offA[mt] + kk * 2);                            \
            uint32_t bf[8][2];                                                 \
            _Pragma("unroll")                                                  \
            for (int np = 0; np < 4; np++) {                                   \
                uint32_t r0, r1, r2, r3;                                       \
                ldsm_x4(r0, r1, r2, r3, bBase + offB[np] + kk * 2);            \
                bf[2 * np + 0][0] = r0; bf[2 * np + 0][1] = r2;                \
                bf[2 * np + 1][0] = r1; bf[2 * np + 1][1] = r3;                \
            }                                                                  \
            _Pragma("unroll")                                                  \
            for (int mt = 0; mt < 2; mt++)                                     \
                _Pragma("unroll")                                              \
                for (int nt = 0; nt < 8; nt++)                                 \
                    mma_f16(acc[mt][nt], af[mt], bf[nt]);                      \
        }                                                                      \
        stage = (stage + 1) % NSTAGE;                                          \
    }

#define ACC_INIT()                                                             \
    float acc[2][8][4];                                                        \
    _Pragma("unroll")                                                          \
    for (int i = 0; i < 2; i++)                                                \
        _Pragma("unroll")                                                      \
        for (int j = 0; j < 8; j++)                                            \
            _Pragma("unroll")                                                  \
            for (int q = 0; q < 4; q++) acc[i][j][q] = 0.0f;

// ---------------- generic fp16 GEMM (Wo / FFN paths) -------------------------
template<int GELU, int RESID, int OUTH>
__global__ __launch_bounds__(256, 2) void gemm_h(
    const __half* __restrict__ A, const __half* __restrict__ BT,
    const float* __restrict__ bias, const float* __restrict__ R,
    float* __restrict__ C, __half* __restrict__ Ch, int K, int N) {
    extern __shared__ __half dsmh[];
    uint32_t dsm0 = smem_u32(dsmh);
    int tid  = threadIdx.x;
    int wid  = tid >> 5, lane = tid & 31;
    int g    = lane >> 2, t = lane & 3;
    int m0   = blockIdx.y * 128;
    int n0   = blockIdx.x * 128;
    int wm   = wid >> 1, wn = wid & 1;
    int mbase = wm * 32, nbase = wn * 64;

    ACC_INIT()
    GEMM_MAINLOOP_H(A, BT, K)

    #pragma unroll
    for (int mt = 0; mt < 2; mt++) {
        #pragma unroll
        for (int nt = 0; nt < 8; nt++) {
            int col = n0 + nbase + nt * 8 + 2 * t;
            float b0 = bias ? bias[col]     : 0.0f;
            float b1 = bias ? bias[col + 1] : 0.0f;
            int r0 = m0 + mbase + mt * 16 + g;
            int r1 = r0 + 8;
            float v00 = acc[mt][nt][0] + b0, v01 = acc[mt][nt][1] + b1;
            float v10 = acc[mt][nt][2] + b0, v11 = acc[mt][nt][3] + b1;
            if (GELU) {
                v00 = gelu_exact(v00); v01 = gelu_exact(v01);
                v10 = gelu_exact(v10); v11 = gelu_exact(v11);
            }
            if (RESID) {
                float2 x0 = *reinterpret_cast<const float2*>(&R[(size_t)r0 * N + col]);
                float2 x1 = *reinterpret_cast<const float2*>(&R[(size_t)r1 * N + col]);
                v00 += x0.x; v01 += x0.y;
                v10 += x1.x; v11 += x1.y;
            }
            if (OUTH) {
                *reinterpret_cast<__half2*>(&Ch[(size_t)r0 * N + col]) =
                    __floats2half2_rn(v00, v01);
                *reinterpret_cast<__half2*>(&Ch[(size_t)r1 * N + col]) =
                    __floats2half2_rn(v10, v11);
            } else {
                *reinterpret_cast<float2*>(&C[(size_t)r0 * N + col]) = make_float2(v00, v01);
                *reinterpret_cast<float2*>(&C[(size_t)r1 * N + col]) = make_float2(v10, v11);
            }
        }
    }
}

// ------------- batched QKV GEMM: z<2 -> fp16 only; z=2 -> fp32 V only --------
__global__ __launch_bounds__(256, 2) void gemm_qkv(
    const __half* __restrict__ Xh, const __half* __restrict__ Wbase,
    const float* __restrict__ b0p, const float* __restrict__ b1p,
    const float* __restrict__ b2p, float* __restrict__ V32,
    __half* __restrict__ QKh) {
    extern __shared__ __half dsmh[];
    uint32_t dsm0 = smem_u32(dsmh);
    int tid  = threadIdx.x;
    int wid  = tid >> 5, lane = tid & 31;
    int g    = lane >> 2, t = lane & 3;
    int m0   = blockIdx.y * 128;
    int n0   = blockIdx.x * 128;
    int z    = blockIdx.z;
    int wm   = wid >> 1, wn = wid & 1;
    int mbase = wm * 32, nbase = wn * 64;

    const __half* BT   = Wbase + (size_t)z * (LNUM * DIM * DIM);
    const float*  bias = (z == 0) ? b0p : (z == 1) ? b1p : b2p;
    __half*       Ch   = (z < 2) ? (QKh + (size_t)z * (TOK * DIM)) : nullptr;

    ACC_INIT()
    GEMM_MAINLOOP_H(Xh, BT, DIM)

    #pragma unroll
    for (int mt = 0; mt < 2; mt++) {
        #pragma unroll
        for (int nt = 0; nt < 8; nt++) {
            int col = n0 + nbase + nt * 8 + 2 * t;
            float b0 = bias[col], b1 = bias[col + 1];
            int r0 = m0 + mbase + mt * 16 + g;
            int r1 = r0 + 8;
            float v00 = acc[mt][nt][0] + b0, v01 = acc[mt][nt][1] + b1;
            float v10 = acc[mt][nt][2] + b0, v11 = acc[mt][nt][3] + b1;
            if (Ch) {
                *reinterpret_cast<__half2*>(&Ch[(size_t)r0 * DIM + col]) =
                    __floats2half2_rn(v00, v01);
                *reinterpret_cast<__half2*>(&Ch[(size_t)r1 * DIM + col]) =
                    __floats2half2_rn(v10, v11);
            } else {
                *reinterpret_cast<float2*>(&V32[(size_t)r0 * DIM + col]) = make_float2(v00, v01);
                *reinterpret_cast<float2*>(&V32[(size_t)r1 * DIM + col]) = make_float2(v10, v11);
            }
        }
    }
}

// ---------------- batched QD/KD GEMM (fp16 in/out) ---------------------------
__global__ __launch_bounds__(256, 2) void gemm_qd(
    const __half* __restrict__ QKh, const __half* __restrict__ dPh,
    __half* __restrict__ QDKD) {
    extern __shared__ __half dsmh[];
    uint32_t dsm0 = smem_u32(dsmh);
    int tid  = threadIdx.x;
    int wid  = tid >> 5, lane = tid & 31;
    int g    = lane >> 2, t = lane & 3;
    int m0   = blockIdx.y * 128;
    int n0   = blockIdx.x * 128;
    int z    = blockIdx.z;
    int wm   = wid >> 1, wn = wid & 1;
    int mbase = wm * 32, nbase = wn * 64;

    const __half* A = QKh + (size_t)z * (TOK * DIM);
    __half*       C = QDKD + (size_t)z * ((size_t)ROWSBH * QCOLS);
    int s0   = (m0 & 1023) >> 2;
    int woff = z ? (224 - s0) : s0;
    const __half* BT = dPh + (size_t)woff * DHD;

    ACC_INIT()
    GEMM_MAINLOOP_H(A, BT, DHD)

    #pragma unroll
    for (int mt = 0; mt < 2; mt++) {
        #pragma unroll
        for (int nt = 0; nt < 8; nt++) {
            int col = n0 + nbase + nt * 8 + 2 * t;
            int r0 = m0 + mbase + mt * 16 + g;
            int r1 = r0 + 8;
            *reinterpret_cast<__half2*>(&C[(size_t)r0 * QCOLS + col]) =
                __floats2half2_rn(acc[mt][nt][0], acc[mt][nt][1]);
            *reinterpret_cast<__half2*>(&C[(size_t)r1 * QCOLS + col]) =
                __floats2half2_rn(acc[mt][nt][2], acc[mt][nt][3]);
        }
    }
}

// ------------- fused attention: fp16 phase 1, tf32 phase 2 -------------------
// smem (floats): P [0,33280) stride 260 (aliases fp16 Q/K staging in
// halves [0,30720)), V0 33280, V1 37504, RED 41728. Total 42240 floats.
#define PST 260
#define VST 132
#define OFF_P   0
#define OFF_V0  33280
#define OFF_V1  37504
#define OFF_RED 41728
#define FUSED_SMEMF 42240
// fp16 staging offsets (halves)
#define HQ0 0
#define HQ1 5120
#define HK0 10240
#define HK1 20480

__global__ __launch_bounds__(256) void fused_attn(
    const __half* __restrict__ QKh, const float* __restrict__ V32,
    const __half* __restrict__ QDKD,
    const float* __restrict__ mask, __half* __restrict__ CTXh) {
    extern __shared__ float dsm[];
    __half* dsmh = reinterpret_cast<__half*>(dsm);
    uint32_t dsm0 = smem_u32(dsm);
    int tid  = threadIdx.x;
    int wid  = tid >> 5, lane = tid & 31;
    int g    = lane >> 2, t = lane & 3;
    int l0   = blockIdx.x * 128;
    int bh   = blockIdx.y;
    int b    = bh >> 2, h = bh & 3;
    int wm   = wid >> 1, wn = wid & 1;
    int mbase = wm * 32;
    int nbase2 = wn * 64;

    const __half* Qb = QKh + (size_t)b * SEQ * DIM + h * DHD;
    const __half* Kb = Qb + (size_t)TOK * DIM;
    const float*  Vb = V32 + (size_t)b * SEQ * DIM + h * DHD;
    const __half* QD = QDKD;
    const __half* KD = QDKD + (size_t)ROWSBH * QCOLS;

    // ---------------- phase 1: S = Q.K^T, fp16 m16n8k16 ---------------------
    float acc[2][16][4];
    #pragma unroll
    for (int i = 0; i < 2; i++)
        #pragma unroll
        for (int j = 0; j < 16; j++)
            #pragma unroll
            for (int q = 0; q < 4; q++) acc[i][j][q] = 0.0f;

    int m_idx  = lane >> 3;
    int fr_row = ((m_idx & 1) << 3) + (lane & 7);
    int fr_col = (m_idx >> 1) << 3;
    uint32_t offQ[2], offK[8];
    #pragma unroll
    for (int mt = 0; mt < 2; mt++)
        offQ[mt] = (uint32_t)(((mbase + mt * 16 + fr_row) * SSTH + fr_col) * 2);
    #pragma unroll
    for (int np = 0; np < 8; np++)
        offK[np] = (uint32_t)(((wn * 128 + np * 16 + fr_row) * SSTH + fr_col) * 2);

    {   // stage chunk 0: Q 128x32h, K 256x32h
        __half* sQ = dsmh + HQ0;
        __half* sK = dsmh + HK0;
        #pragma unroll
        for (int i = 0; i < 2; i++) {
            int idx = tid + i * 256, row = idx >> 2, seg = idx & 3;
            cp16(smem_u32(sQ + row * SSTH + seg * 8),
                 &Qb[(size_t)(l0 + row) * DIM + seg * 8]);
        }
        #pragma unroll
        for (int i = 0; i < 4; i++) {
            int idx = tid + i * 256, row = idx >> 2, seg = idx & 3;
            cp16(smem_u32(sK + row * SSTH + seg * 8),
                 &Kb[(size_t)row * DIM + seg * 8]);
        }
        CP_COMMIT();
    }
    for (int c = 0; c < 4; c++) {
        if (c + 1 < 4) {
            __half* sQ = dsmh + ((c + 1) & 1 ? HQ1 : HQ0);
            __half* sK = dsmh + ((c + 1) & 1 ? HK1 : HK0);
            #pragma unroll
            for (int i = 0; i < 2; i++) {
                int idx = tid + i * 256, row = idx >> 2, seg = idx & 3;
                cp16(smem_u32(sQ + row * SSTH + seg * 8),
                     &Qb[(size_t)(l0 + row) * DIM + (c + 1) * 32 + seg * 8]);
            }
            #pragma unroll
            for (int i = 0; i < 4; i++) {
                int idx = tid + i * 256, row = idx >> 2, seg = idx & 3;
                cp16(smem_u32(sK + row * SSTH + seg * 8),
                     &Kb[(size_t)row * DIM + (c + 1) * 32 + seg * 8]);
            }
            CP_COMMIT();
        } else {
            CP_COMMIT();
        }
        CP_WAIT1();
        __syncthreads();
        uint32_t qBase = dsm0 + (uint32_t)(((c & 1) ? HQ1 : HQ0) * 2);
        uint32_t kBase = dsm0 + (uint32_t)(((c & 1) ? HK1 : HK0) * 2);
        #pragma unroll
        for (int kk = 0; kk < 32; kk += 16) {
            uint32_t af[2][4];
            #pragma unroll
            for (int mt = 0; mt < 2; mt++)
                ldsm_x4(af[mt][0], af[mt][1], af[mt][2], af[mt][3],
                        qBase + offQ[mt] + kk * 2);
            #pragma unroll
            for (int np = 0; np < 8; np++) {
                uint32_t r0, r1, r2, r3;
                ldsm_x4(r0, r1, r2, r3, kBase + offK[np] + kk * 2);
                uint32_t bf0[2] = {r0, r2};
                uint32_t bf1[2] = {r1, r3};
                #pragma unroll
                for (int mt = 0; mt < 2; mt++) {
                    mma_f16(acc[mt][2 * np + 0], af[mt], bf0);
                    mma_f16(acc[mt][2 * np + 1], af[mt], bf1);
                }
            }
        }
        __syncthreads();
    }

    // ------------- epilogue: gathers + scale + mask (unchanged) -------------
    #pragma unroll
    for (int mt = 0; mt < 2; mt++) {
        int ll0 = l0 + mbase + mt * 16 + g;
        int ll1 = ll0 + 8;
        size_t qdr0 = ((size_t)(b * SEQ + ll0) * NHEAD + h) * QCOLS;
        size_t qdr1 = ((size_t)(b * SEQ + ll1) * NHEAD + h) * QCOLS;
        #pragma unroll
        for (int nt = 0; nt < 16; nt++) {
            int rr0 = wn * 128 + nt * 8 + 2 * t;
            int rr1 = rr0 + 1;
            size_t kdr0 = ((size_t)(b * SEQ + rr0) * NHEAD + h) * QCOLS;
            size_t kdr1 = ((size_t)(b * SEQ + rr1) * NHEAD + h) * QCOLS;
            float bias0 = (1.0f - mask[b * SEQ + rr0]) * (-1e9f);
            float bias1 = (1.0f - mask[b * SEQ + rr1]) * (-1e9f);
            int jq00 = (ll0 & 31) + 255 - rr0, jq01 = jq00 - 1;
            int jq10 = (ll1 & 31) + 255 - rr0, jq11 = jq10 - 1;
            int jk00 = ll0 - (rr0 & 31) + 31,  jk01 = ll0 - (rr1 & 31) + 31;
            int jk10 = ll1 - (rr0 & 31) + 31,  jk11 = ll1 - (rr1 & 31) + 31;
            float qd00 = __half2float(QD[qdr0 + jq00]);
            float qd01 = __half2float(QD[qdr0 + jq01]);
            float qd10 = __half2float(QD[qdr1 + jq10]);
            float qd11 = __half2float(QD[qdr1 + jq11]);
            float kd00 = __half2float(KD[kdr0 + jk00]);
            float kd01 = __half2float(KD[kdr1 + jk01]);
            float kd10 = __half2float(KD[kdr0 + jk10]);
            float kd11 = __half2float(KD[kdr1 + jk11]);
            acc[mt][nt][0] = (acc[mt][nt][0] + qd00 + kd00) * SM_SCALE + bias0;
            acc[mt][nt][1] = (acc[mt][nt][1] + qd01 + kd01) * SM_SCALE + bias1;
            acc[mt][nt][2] = (acc[mt][nt][2] + qd10 + kd10) * SM_SCALE + bias0;
            acc[mt][nt][3] = (acc[mt][nt][3] + qd11 + kd11) * SM_SCALE + bias1;
        }
    }

    float* rmax = dsm + OFF_RED;
    float* rsum = dsm + OFF_RED + 256;
    float mx[2][2];
    #pragma unroll
    for (int mt = 0; mt < 2; mt++)
        #pragma unroll
        for (int hf = 0; hf < 2; hf++) {
            float m = -1e30f;
            #pragma unroll
            for (int nt = 0; nt < 16; nt++) {
                m = fmaxf(m, acc[mt][nt][hf * 2]);
                m = fmaxf(m, acc[mt][nt][hf * 2 + 1]);
            }
            m = fmaxf(m, __shfl_xor_sync(0xffffffffu, m, 1));
            m = fmaxf(m, __shfl_xor_sync(0xffffffffu, m, 2));
            mx[mt][hf] = m;
        }
    if (t == 0) {
        #pragma unroll
        for (int mt = 0; mt < 2; mt++)
            #pragma unroll
            for (int hf = 0; hf < 2; hf++) {
                int lrow = mbase + mt * 16 + hf * 8 + g;
                rmax[wn * 128 + lrow] = mx[mt][hf];
            }
    }
    __syncthreads();
    #pragma unroll
    for (int mt = 0; mt < 2; mt++)
        #pragma unroll
        for (int hf = 0; hf < 2; hf++) {
            int lrow = mbase + mt * 16 + hf * 8 + g;
            float m = fmaxf(rmax[lrow], rmax[128 + lrow]);
            float s = 0.0f;
            #pragma unroll
            for (int nt = 0; nt < 16; nt++) {
                float e0 = __expf(acc[mt][nt][hf * 2]     - m);
                float e1 = __expf(acc[mt][nt][hf * 2 + 1] - m);
                acc[mt][nt][hf * 2]     = e0;
                acc[mt][nt][hf * 2 + 1] = e1;
                s += e0 + e1;
            }
            s += __shfl_xor_sync(0xffffffffu, s, 1);
            s += __shfl_xor_sync(0xffffffffu, s, 2);
            if (t == 0) rsum[wn * 128 + lrow] = s;
        }
    __syncthreads();
    #pragma unroll
    for (int mt = 0; mt < 2; mt++)
        #pragma unroll
        for (int hf = 0; hf < 2; hf++) {
            int lrow = mbase + mt * 16 + hf * 8 + g;
            float inv = 1.0f / (rsum[lrow] + rsum[128 + lrow]);
            #pragma unroll
            for (int nt = 0; nt < 16; nt++) {
                acc[mt][nt][hf * 2]     *= inv;
                acc[mt][nt][hf * 2 + 1] *= inv;
            }
        }
    __syncthreads();

    // -------------------------- write P (fp32) to smem -----------------------
    float* P = dsm + OFF_P;
    #pragma unroll
    for (int mt = 0; mt < 2; mt++) {
        int lr0 = mbase + mt * 16 + g;
        int lr1 = lr0 + 8;
        #pragma unroll
        for (int nt = 0; nt < 16; nt++) {
            int col = wn * 128 + nt * 8 + 2 * t;
            *reinterpret_cast<float2*>(&P[lr0 * PST + col]) =
                make_float2(acc[mt][nt][0], acc[mt][nt][1]);
            *reinterpret_cast<float2*>(&P[lr1 * PST + col]) =
                make_float2(acc[mt][nt][2], acc[mt][nt][3]);
        }
    }
    __syncthreads();

    // ------------------- phase 2: ctx = P @ V (tf32, unchanged) --------------
    float acc2[2][8][4];
    #pragma unroll
    for (int i = 0; i < 2; i++)
        #pragma unroll
        for (int j = 0; j < 8; j++)
            #pragma unroll
            for (int q = 0; q < 4; q++) acc2[i][j][q] = 0.0f;

    {
        float* sV = dsm + OFF_V0;
        #pragma unroll
        for (int i = 0; i < 4; i++) {
            int idx = tid + i * 256, r = idx >> 5, dseg = idx & 31;
            cp16(smem_u32(sV + r * VST + dseg * 4),
                 &Vb[(size_t)r * DIM + dseg * 4]);
        }
        CP_COMMIT();
    }
    for (int c = 0; c < 8; c++) {
        if (c + 1 < 8) {
            float* sV = dsm + (((c + 1) & 1) ? OFF_V1 : OFF_V0);
            #pragma unroll
            for (int i = 0; i < 4; i++) {
                int idx = tid + i * 256, r = idx >> 5, dseg = idx & 31;
                cp16(smem_u32(sV + r * VST + dseg * 4),
                     &Vb[(size_t)((c + 1) * 32 + r) * DIM + dseg * 4]);
            }
            CP_COMMIT();
        } else {
            CP_COMMIT();
        }
        CP_WAIT1();
        __syncthreads();
        const uint32_t* sP = (const uint32_t*)P;
        const uint32_t* sV = (const uint32_t*)(dsm + ((c & 1) ? OFF_V1 : OFF_V0));
        #pragma unroll
        for (int kk = 0; kk < 32; kk += 8) {
            uint32_t af[2][4];
            #pragma unroll
            for (int mt = 0; mt < 2; mt++) {
                int r = mbase + mt * 16 + g;
                af[mt][0] = sP[r * PST + c * 32 + kk + t];
                af[mt][1] = sP[(r + 8) * PST + c * 32 + kk + t];
                af[mt][2] = sP[r * PST + c * 32 + kk + t + 4];
                af[mt][3] = sP[(r + 8) * PST + c * 32 + kk + t + 4];
            }
            uint32_t bf[8][2];
            #pragma unroll
            for (int nt = 0; nt < 8; nt++) {
                int d = nbase2 + nt * 8 + g;
                bf[nt][0] = sV[(kk + t) * VST + d];
                bf[nt][1] = sV[(kk + t + 4) * VST + d];
            }
            #pragma unroll
            for (int mt = 0; mt < 2; mt++)
                #pragma unroll
                for (int nt = 0; nt < 8; nt++)
                    mma_tf32(acc2[mt][nt], af[mt], bf[nt]);
        }
        __syncthreads();
    }

    #pragma unroll
    for (int mt = 0; mt < 2; mt++) {
        #pragma unroll
        for (int nt = 0; nt < 8; nt++) {
            int col = nbase2 + nt * 8 + 2 * t;
            int rr0 = l0 + mbase + mt * 16 + g;
            int rr1 = rr0 + 8;
            *reinterpret_cast<__half2*>(&CTXh[(size_t)(b * SEQ + rr0) * DIM + h * DHD + col]) =
                __floats2half2_rn(acc2[mt][nt][0], acc2[mt][nt][1]);
            *reinterpret_cast<__half2*>(&CTXh[(size_t)(b * SEQ + rr1) * DIM + h * DHD + col]) =
                __floats2half2_rn(acc2[mt][nt][2], acc2[mt][nt][3]);
        }
    }
}

// ---------------- fused weight prep: transposes -> fp16 ---------------------
__global__ void wprep(const float* __restrict__ Wq, const float* __restrict__ Wk,
                      const float* __restrict__ Wv, const float* __restrict__ Wo,
                      const float* __restrict__ Wi, const float* __restrict__ Wo2,
                      const float* __restrict__ dist,
                      __half* __restrict__ WqkvTh, __half* __restrict__ WoTh,
                      __half* __restrict__ WiTh, __half* __restrict__ Wo2Th,
                      __half* __restrict__ dPh) {
    int z = blockIdx.z;
    int i = blockIdx.x * 256 + threadIdx.x;
    if (z < 3) {
        const float* S = (z == 0) ? Wq : (z == 1) ? Wk : Wv;
        __half* D = WqkvTh + (size_t)z * (LNUM * DIM * DIM);
        int l = i >> 18;
        int w = i & 262143;
        int k = w >> 9, n = w & 511;
        D[(size_t)l * 262144 + n * 512 + k] = __float2half_rn(S[i]);
    } else if (z == 3) {
        int l = i >> 18;
        int w = i & 262143;
        int k = w >> 9, n = w & 511;
        WoTh[(size_t)l * 262144 + n * 512 + k] = __float2half_rn(Wo[i]);
    } else if (z == 4) {
        if (i < LNUM * DIM * FFI) {
            int l = i >> 16, w = i & 65535;
            int k = w >> 7, n = w & 127;
            WiTh[(size_t)l * 65536 + n * 512 + k] = __float2half_rn(Wi[i]);
        }
    } else if (z == 5) {
        if (i < LNUM * FFI * DIM) {
            int l = i >> 16, w = i & 65535;
            int k = w >> 9, n = w & 511;
            Wo2Th[(size_t)l * 65536 + n * 128 + k] = __float2half_rn(Wo2[i]);
        }
    } else {
        if (i < DPAD * DHD) {
            int pp = i >> 7;
            dPh[i] = (pp < 511) ? __float2half_rn(dist[i]) : __float2half_rn(0.0f);
        }
    }
}

// --------------------------- embedding + LN ---------------------------------
__device__ __forceinline__ void block_reduce2(float& a, float& b) {
    __shared__ float sa[8], sb[8];
    int lane = threadIdx.x & 31, w = threadIdx.x >> 5;
    #pragma unroll
    for (int o = 16; o; o >>= 1) {
        a += __shfl_xor_sync(0xffffffffu, a, o);
        b += __shfl_xor_sync(0xffffffffu, b, o);
    }
    if (lane == 0) { sa[w] = a; sb[w] = b; }
    __syncthreads();
    if (w == 0) {
        a = (lane < 8) ? sa[lane] : 0.0f;
        b = (lane < 8) ? sb[lane] : 0.0f;
        #pragma unroll
        for (int o = 4; o; o >>= 1) {
            a += __shfl_xor_sync(0xffffffffu, a, o);
            b += __shfl_xor_sync(0xffffffffu, b, o);
        }
        if (lane == 0) { sa[0] = a; sb[0] = b; }
    }
    __syncthreads();
    a = sa[0]; b = sb[0];
}

__global__ void embed_ln(const int* __restrict__ ids, const float* __restrict__ inW,
                         const float* __restrict__ inb, const float* __restrict__ tok,
                         const float* __restrict__ g,  const float* __restrict__ bb,
                         float* __restrict__ X, __half* __restrict__ Xh) {
    int tt = blockIdx.x, tid = threadIdx.x;
    float f[NFEAT];
    #pragma unroll
    for (int i = 0; i < NFEAT; i++) f[i] = (float)ids[tt * NFEAT + i];
    int d0 = tid, d1 = tid + 256;
    float v0 = inb[d0] + tok[d0];
    float v1 = inb[d1] + tok[d1];
    #pragma unroll
    for (int i = 0; i < NFEAT; i++) {
        v0 += f[i] * inW[i * DIM + d0];
        v1 += f[i] * inW[i * DIM + d1];
    }
    float s = v0 + v1, q = v0 * v0 + v1 * v1;
    block_reduce2(s, q);
    float mu  = s * (1.0f / DIM);
    float var = q * (1.0f / DIM) - mu * mu;
    float r   = rsqrtf(var + 1e-12f);
    float o0 = (v0 - mu) * r * g[d0] + bb[d0];
    float o1 = (v1 - mu) * r * g[d1] + bb[d1];
    size_t base = (size_t)tt * DIM;
    X[base + d0] = o0;  X[base + d1] = o1;
    Xh[base + d0] = __float2half_rn(o0);
    Xh[base + d1] = __float2half_rn(o1);
}

// warp-per-token pure LayerNorm, dual fp32+fp16 output
__global__ __launch_bounds__(256) void ln_w(
    const float* __restrict__ in,
    const float* __restrict__ g, const float* __restrict__ bb,
    float* __restrict__ out, __half* __restrict__ outh) {
    int wid = threadIdx.x >> 5, lane = threadIdx.x & 31;
    int tt = blockIdx.x * 8 + wid;
    size_t base = (size_t)tt * DIM;
    float4 v[4];
    float s = 0.0f, q = 0.0f;
    #pragma unroll
    for (int i = 0; i < 4; i++) {
        int col = i * 128 + lane * 4;
        v[i] = *reinterpret_cast<const float4*>(&in[base + col]);
        s += v[i].x + v[i].y + v[i].z + v[i].w;
        q += v[i].x * v[i].x + v[i].y * v[i].y + v[i].z * v[i].z + v[i].w * v[i].w;
    }
    #pragma unroll
    for (int o = 16; o; o >>= 1) {
        s += __shfl_xor_sync(0xffffffffu, s, o);
        q += __shfl_xor_sync(0xffffffffu, q, o);
    }
    float mu  = s * (1.0f / DIM);
    float var = q * (1.0f / DIM) - mu * mu;
    float r   = rsqrtf(var + 1e-12f);
    #pragma unroll
    for (int i = 0; i < 4; i++) {
        int col = i * 128 + lane * 4;
        float4 g4 = *reinterpret_cast<const float4*>(&g[col]);
        float4 b4 = *reinterpret_cast<const float4*>(&bb[col]);
        float4 o4;
        o4.x = (v[i].x - mu) * r * g4.x + b4.x;
        o4.y = (v[i].y - mu) * r * g4.y + b4.y;
        o4.z = (v[i].z - mu) * r * g4.z + b4.z;
        o4.w = (v[i].w - mu) * r * g4.w + b4.w;
        *reinterpret_cast<float4*>(&out[base + col]) = o4;
        __half2 h0 = __floats2half2_rn(o4.x, o4.y);
        __half2 h1 = __floats2half2_rn(o4.z, o4.w);
        *reinterpret_cast<__half2*>(&outh[base + col])     = h0;
        *reinterpret_cast<__half2*>(&outh[base + col + 2]) = h1;
    }
}

// ------------------------------ host driver ----------------------------------
extern "C" void kernel_launch(void* const* d_in, const int* in_sizes, int n_in,
                              void* d_out, int out_size) {
    (void)in_sizes; (void)n_in; (void)out_size;
    const int*   ids  = (const int*)  d_in[0];
    const float* mask = (const float*)d_in[1];
    const float* inW  = (const float*)d_in[2];
    const float* inb  = (const float*)d_in[3];
    const float* tok  = (const float*)d_in[4];
    const float* elg  = (const float*)d_in[5];
    const float* elb  = (const float*)d_in[6];
    const float* dist = (const float*)d_in[7];
    const float* Wq   = (const float*)d_in[8];
    const float* bq   = (const float*)d_in[9];
    const float* Wk   = (const float*)d_in[10];
    const float* bk   = (const float*)d_in[11];
    const float* Wv   = (const float*)d_in[12];
    const float* bv   = (const float*)d_in[13];
    const float* Wo   = (const float*)d_in[14];
    const float* bo   = (const float*)d_in[15];
    const float* ln1g = (const float*)d_in[16];
    const float* ln1b = (const float*)d_in[17];
    const float* Wi   = (const float*)d_in[18];
    const float* bi   = (const float*)d_in[19];
    const float* Wo2  = (const float*)d_in[20];
    const float* bo2  = (const float*)d_in[21];
    const float* ln2g = (const float*)d_in[22];
    const float* ln2b = (const float*)d_in[23];
    float* out = (float*)d_out;

    float *X, *V32, *TMP;
    __half *Xh, *QKh, *CTXh, *Hbh, *QDKD, *dPh;
    __half *WqkvTh, *WoTh, *WiTh, *Wo2Th;
    cudaGetSymbolAddress((void**)&X,      g_X);
    cudaGetSymbolAddress((void**)&Xh,     g_Xh);
    cudaGetSymbolAddress((void**)&V32,    g_V32);
    cudaGetSymbolAddress((void**)&QKh,    g_QKh);
    cudaGetSymbolAddress((void**)&CTXh,   g_CTXh);
    cudaGetSymbolAddress((void**)&TMP,    g_TMP);
    cudaGetSymbolAddress((void**)&Hbh,    g_Hbh);
    cudaGetSymbolAddress((void**)&QDKD,   g_QDKD);
    cudaGetSymbolAddress((void**)&dPh,    g_dPh);
    cudaGetSymbolAddress((void**)&WqkvTh, g_WqkvTh);
    cudaGetSymbolAddress((void**)&WoTh,   g_WoTh);
    cudaGetSymbolAddress((void**)&WiTh,   g_WiTh);
    cudaGetSymbolAddress((void**)&Wo2Th,  g_Wo2Th);

    const int FUSED_SMEM = FUSED_SMEMF * 4;
    cudaFuncSetAttribute(gemm_h<0,1,0>, cudaFuncAttributeMaxDynamicSharedMemorySize, GEMM_SMEM_H);
    cudaFuncSetAttribute(gemm_h<1,0,1>, cudaFuncAttributeMaxDynamicSharedMemorySize, GEMM_SMEM_H);
    cudaFuncSetAttribute(gemm_qkv,      cudaFuncAttributeMaxDynamicSharedMemorySize, GEMM_SMEM_H);
    cudaFuncSetAttribute(gemm_qd,       cudaFuncAttributeMaxDynamicSharedMemorySize, GEMM_SMEM_H);
    cudaFuncSetAttribute(fused_attn,    cudaFuncAttributeMaxDynamicSharedMemorySize, FUSED_SMEM);

    wprep<<<dim3(4096, 1, 7), 256>>>(Wq, Wk, Wv, Wo, Wi, Wo2, dist,
                                     WqkvTh, WoTh, WiTh, Wo2Th, dPh);
    embed_ln<<<TOK, 256>>>(ids, inW, inb, tok, elg, elb, X, Xh);

    dim3 gQKV(DIM / 128, TOK / 128, 3);
    dim3 gQD(QCOLS / 128, ROWSBH / 128, 2);
    dim3 gG(DIM / 128, TOK / 128);
    dim3 gGi(FFI / 128, TOK / 128);
    dim3 gA(SEQ / 128, BATCH * NHEAD);

    for (int l = 0; l < LNUM; l++) {
        const __half* wqkv = WqkvTh + (size_t)l * DIM * DIM;
        const __half* wot  = WoTh   + (size_t)l * DIM * DIM;
        const __half* wit  = WiTh   + (size_t)l * FFI * DIM;
        const __half* wo2t = Wo2Th  + (size_t)l * DIM * FFI;

        gemm_qkv<<<gQKV, 256, GEMM_SMEM_H>>>(Xh, wqkv, bq + l * DIM, bk + l * DIM,
                                             bv + l * DIM, V32, QKh);
        gemm_qd<<<gQD, 256, GEMM_SMEM_H>>>(QKh, dPh, QDKD);

        fused_attn<<<gA, 256, FUSED_SMEM>>>(QKh, V32, QDKD, mask, CTXh);

        gemm_h<0,1,0><<<gG, 256, GEMM_SMEM_H>>>(CTXh, wot, bo + l * DIM, X,
                                                TMP, nullptr, DIM, DIM);
        ln_w<<<TOK / 8, 256>>>(TMP, ln1g + l * DIM, ln1b + l * DIM, X, Xh);

        gemm_h<1,0,1><<<gGi, 256, GEMM_SMEM_H>>>(Xh, wit, bi + l * FFI, nullptr,
                                                 nullptr, Hbh, DIM, FFI);
        gemm_h<0,1,0><<<gG, 256, GEMM_SMEM_H>>>(Hbh, wo2t, bo2 + l * DIM, X,
                                                TMP, nullptr, FFI, DIM);
        ln_w<<<TOK / 8, 256>>>(TMP, ln2g + l * DIM, ln2b + l * DIM,
                               (l == LNUM - 1) ? out : X, Xh);
    }
}